// round 13
// baseline (speedup 1.0000x reference)
#include <cuda_runtime.h>
#include <cuda_fp16.h>
#include <math.h>
#include <stdint.h>

#define T_TOK 8192
#define H_DIM 1024
#define I_DIM 4096
#define S_DIM 128
#define E_NUM 16384
#define TOPK  16

// ---------------- scratch ----------------
__device__ __align__(16) __half g_xh  [(size_t)T_TOK * H_DIM];
__device__ __align__(16) __half g_wgu [(size_t)2 * I_DIM * H_DIM];   // interleaved [wg_j; wu_j]
__device__ __align__(16) __half g_wdh [(size_t)H_DIM * I_DIM];
__device__ __align__(16) __half g_wrh [(size_t)2 * S_DIM * H_DIM];   // [wrx; wry]
__device__ __align__(16) __half g_ueh [(size_t)E_NUM * H_DIM];
__device__ __align__(16) __half g_deh [(size_t)E_NUM * H_DIM];
__device__ __align__(16) __half g_hh  [(size_t)T_TOK * I_DIM];
__device__ __align__(16) float  g_gxy [(size_t)T_TOK * 2 * S_DIM];   // [T, 256]
__device__ __align__(16) float  g_bnp [128 * 512];
__device__ __align__(16) float  g_bn  [4 * S_DIM];
__device__ __align__(16) int    g_ti  [(size_t)T_TOK * TOPK];
__device__ __align__(16) float  g_tw  [(size_t)T_TOK * TOPK];

// ---------------- PTX helpers (sm_80-compatible only) ----------------
__device__ __forceinline__ uint32_t s2u(const void* p) {
    uint32_t a;
    asm("{ .reg .u64 t; cvta.to.shared.u64 t, %1; cvt.u32.u64 %0, t; }" : "=r"(a) : "l"(p));
    return a;
}
__device__ __forceinline__ void cp16(uint32_t dst, const void* src) {
    asm volatile("cp.async.cg.shared.global [%0], [%1], 16;" :: "r"(dst), "l"(src));
}
#define CP_COMMIT() asm volatile("cp.async.commit_group;" ::: "memory")
#define CP_WAIT(N)  asm volatile("cp.async.wait_group %0;" :: "n"(N) : "memory")

__device__ __forceinline__ void ldm4(uint32_t* r, uint32_t addr) {
    asm volatile("ldmatrix.sync.aligned.m8n8.x4.shared.b16 {%0,%1,%2,%3}, [%4];"
                 : "=r"(r[0]), "=r"(r[1]), "=r"(r[2]), "=r"(r[3]) : "r"(addr));
}
__device__ __forceinline__ void mma16816(float* c, const uint32_t* a, uint32_t b0, uint32_t b1) {
    asm volatile("mma.sync.aligned.m16n8k16.row.col.f32.f16.f16.f32 "
                 "{%0,%1,%2,%3}, {%4,%5,%6,%7}, {%8,%9}, {%0,%1,%2,%3};"
                 : "+f"(c[0]), "+f"(c[1]), "+f"(c[2]), "+f"(c[3])
                 : "r"(a[0]), "r"(a[1]), "r"(a[2]), "r"(a[3]), "r"(b0), "r"(b1));
}
// fp16-accumulate variant: D,C are 2x .f16x2 regs
__device__ __forceinline__ void mma16816h(uint32_t* c, const uint32_t* a, uint32_t b0, uint32_t b1) {
    asm volatile("mma.sync.aligned.m16n8k16.row.col.f16.f16.f16.f16 "
                 "{%0,%1}, {%2,%3,%4,%5}, {%6,%7}, {%0,%1};"
                 : "+r"(c[0]), "+r"(c[1])
                 : "r"(a[0]), "r"(a[1]), "r"(a[2]), "r"(a[3]), "r"(b0), "r"(b1));
}

// smem tile: 128 rows x 32 f16 (64B/row); chunk = 16B of 8 f16.
// swizzle: chunk' = chunk ^ ((row>>1)&3)
__device__ __forceinline__ uint32_t tile_off(int row, int chunk) {
    return (uint32_t)row * 64u + (uint32_t)((chunk ^ ((row >> 1) & 3)) * 16);
}

// ---------------- fp32 -> fp16 (2x ILP) ----------------
__global__ void conv_half(const float4* __restrict__ in, __half2* __restrict__ o, int n4)
{
    const int stride = gridDim.x * blockDim.x;
    int i = blockIdx.x * blockDim.x + threadIdx.x;
    for (; i + stride < n4; i += 2 * stride) {
        float4 v0 = in[i];
        float4 v1 = in[i + stride];
        o[2 * i]     = __half2{__float2half_rn(v0.x), __float2half_rn(v0.y)};
        o[2 * i + 1] = __half2{__float2half_rn(v0.z), __float2half_rn(v0.w)};
        o[2 * (i + stride)]     = __half2{__float2half_rn(v1.x), __float2half_rn(v1.y)};
        o[2 * (i + stride) + 1] = __half2{__float2half_rn(v1.z), __float2half_rn(v1.w)};
    }
    if (i < n4) {
        float4 v = in[i];
        o[2 * i]     = __half2{__float2half_rn(v.x), __float2half_rn(v.y)};
        o[2 * i + 1] = __half2{__float2half_rn(v.z), __float2half_rn(v.w)};
    }
}

// interleave wg/wu rows: W'[2j] = wg[j], W'[2j+1] = wu[j]  (fp32 -> fp16)
__global__ void conv_interleave(const float4* __restrict__ wg, const float4* __restrict__ wu,
                                __half2* __restrict__ o, int n4)   // n4 = I*H/4
{
    constexpr int H4 = H_DIM / 4;
    for (int i = blockIdx.x * blockDim.x + threadIdx.x; i < n4; i += gridDim.x * blockDim.x) {
        int row = i / H4, c = i % H4;
        float4 g = wg[i], u = wu[i];
        size_t dg = (size_t)(2 * row) * H4 + c;
        size_t du = (size_t)(2 * row + 1) * H4 + c;
        o[2 * dg]     = __half2{__float2half_rn(g.x), __float2half_rn(g.y)};
        o[2 * dg + 1] = __half2{__float2half_rn(g.z), __float2half_rn(g.w)};
        o[2 * du]     = __half2{__float2half_rn(u.x), __float2half_rn(u.y)};
        o[2 * du + 1] = __half2{__float2half_rn(u.z), __float2half_rn(u.w)};
    }
}

// ---------------------------------------------------------------------------
// fp32-accumulate GEMM (measured-best config) — used for router + down GEMMs.
// EPI: 0 = C = D;  2 = C += D
// ---------------------------------------------------------------------------
template<int EPI>
__global__ void __launch_bounds__(256, 2)
gemm_mma(const __half* __restrict__ A, const __half* __restrict__ B,
         int K, int niter, int N,
         float* __restrict__ C)
{
    constexpr uint32_t TILE = 128 * 64;
    constexpr uint32_t STAGE = 2 * TILE;
    extern __shared__ char smem[];
    const uint32_t sbase = s2u(smem);

    const int tid  = threadIdx.x;
    const int lane = tid & 31;
    const int wid  = tid >> 5;
    const int wm   = wid >> 1;
    const int wn   = wid & 1;
    const int bm   = blockIdx.y * 128;
    const int bn   = blockIdx.x * 128;

    const int prow = tid >> 1;
    const int pc0  = (tid & 1) * 2;
    const uint32_t pa_off0 = tile_off(prow, pc0);
    const uint32_t pa_off1 = tile_off(prow, pc0 + 1);

    const int lrow8 = ((lane >> 3) & 1) * 8 + (lane & 7);
    const int lchnk = lane >> 4;
    uint32_t a_off[2], b_off[4];
#pragma unroll
    for (int mt = 0; mt < 2; mt++)
        a_off[mt] = tile_off(wm * 32 + mt * 16 + lrow8, lchnk);
#pragma unroll
    for (int p = 0; p < 4; p++)
        b_off[p] = tile_off(wn * 64 + p * 16 + lrow8, lchnk);

    float acc[2][8][4];
#pragma unroll
    for (int mt = 0; mt < 2; mt++)
#pragma unroll
        for (int nt = 0; nt < 8; nt++)
#pragma unroll
            for (int q = 0; q < 4; q++) acc[mt][nt][q] = 0.f;

    auto load_stage = [&](int j) {
        const int kk = j * 32;
        const uint32_t sa = sbase + (uint32_t)(j % 3) * STAGE;
        const uint32_t sb = sa + TILE;
        const __half* ga = A + (size_t)(bm + prow) * K + kk + pc0 * 8;
        const __half* gb = B + (size_t)(bn + prow) * K + kk + pc0 * 8;
        cp16(sa + pa_off0, ga);
        cp16(sa + pa_off1, ga + 8);
        cp16(sb + pa_off0, gb);
        cp16(sb + pa_off1, gb + 8);
    };

    load_stage(0); CP_COMMIT();
    load_stage(1); CP_COMMIT();

    for (int j = 0; j < niter; ++j) {
        CP_WAIT(1);
        __syncthreads();
        if (j + 2 < niter) load_stage(j + 2);
        CP_COMMIT();

        const uint32_t sa = sbase + (uint32_t)(j % 3) * STAGE;
        const uint32_t sb = sa + TILE;
#pragma unroll
        for (int ks = 0; ks < 2; ks++) {
            const uint32_t kx = ks ? 32u : 0u;
            uint32_t a[2][4], b[4][4];
#pragma unroll
            for (int mt = 0; mt < 2; mt++) ldm4(a[mt], sa + (a_off[mt] ^ kx));
#pragma unroll
            for (int p = 0; p < 4; p++)    ldm4(b[p], sb + (b_off[p] ^ kx));
#pragma unroll
            for (int mt = 0; mt < 2; mt++)
#pragma unroll
                for (int p = 0; p < 4; p++) {
                    mma16816(acc[mt][2 * p],     a[mt], b[p][0], b[p][2]);
                    mma16816(acc[mt][2 * p + 1], a[mt], b[p][1], b[p][3]);
                }
        }
    }

    const int gid  = lane >> 2;
    const int tid4 = lane & 3;
#pragma unroll
    for (int mt = 0; mt < 2; mt++) {
        const int r0 = bm + wm * 32 + mt * 16 + gid;
        const int r1 = r0 + 8;
#pragma unroll
        for (int nt = 0; nt < 8; nt++) {
            const int col = bn + wn * 64 + nt * 8 + tid4 * 2;
            float v00 = acc[mt][nt][0], v01 = acc[mt][nt][1];
            float v10 = acc[mt][nt][2], v11 = acc[mt][nt][3];
            if (EPI == 0) {
                *(float2*)(C + (size_t)r0 * N + col) = make_float2(v00, v01);
                *(float2*)(C + (size_t)r1 * N + col) = make_float2(v10, v11);
            } else {
                float2 c0 = *(float2*)(C + (size_t)r0 * N + col);
                float2 c1 = *(float2*)(C + (size_t)r1 * N + col);
                *(float2*)(C + (size_t)r0 * N + col) = make_float2(c0.x + v00, c0.y + v01);
                *(float2*)(C + (size_t)r1 * N + col) = make_float2(c1.x + v10, c1.y + v11);
            }
        }
    }
}

// ---------------------------------------------------------------------------
// Gateup GEMM with fp16-accumulate HMMA (2x issue rate if HW supports),
// promoted to fp32 master accumulators every K=32 chunk.
// Epilogue: interleaved gate/up -> h = silu(gate)*up -> Hh fp16.
// ---------------------------------------------------------------------------
__global__ void __launch_bounds__(256, 2)
gemm_gateup_h(const __half* __restrict__ A, const __half* __restrict__ B,
              int K, int niter, int N, __half* __restrict__ Hh)
{
    constexpr uint32_t TILE = 128 * 64;
    constexpr uint32_t STAGE = 2 * TILE;
    extern __shared__ char smem[];
    const uint32_t sbase = s2u(smem);

    const int tid  = threadIdx.x;
    const int lane = tid & 31;
    const int wid  = tid >> 5;
    const int wm   = wid >> 1;
    const int wn   = wid & 1;
    const int bm   = blockIdx.y * 128;
    const int bn   = blockIdx.x * 128;

    const int prow = tid >> 1;
    const int pc0  = (tid & 1) * 2;
    const uint32_t pa_off0 = tile_off(prow, pc0);
    const uint32_t pa_off1 = tile_off(prow, pc0 + 1);

    const int lrow8 = ((lane >> 3) & 1) * 8 + (lane & 7);
    const int lchnk = lane >> 4;
    uint32_t a_off[2], b_off[4];
#pragma unroll
    for (int mt = 0; mt < 2; mt++)
        a_off[mt] = tile_off(wm * 32 + mt * 16 + lrow8, lchnk);
#pragma unroll
    for (int p = 0; p < 4; p++)
        b_off[p] = tile_off(wn * 64 + p * 16 + lrow8, lchnk);

    float acc[2][8][4];
#pragma unroll
    for (int mt = 0; mt < 2; mt++)
#pragma unroll
        for (int nt = 0; nt < 8; nt++)
#pragma unroll
            for (int q = 0; q < 4; q++) acc[mt][nt][q] = 0.f;

    auto load_stage = [&](int j) {
        const int kk = j * 32;
        const uint32_t sa = sbase + (uint32_t)(j % 3) * STAGE;
        const uint32_t sb = sa + TILE;
        const __half* ga = A + (size_t)(bm + prow) * K + kk + pc0 * 8;
        const __half* gb = B + (size_t)(bn + prow) * K + kk + pc0 * 8;
        cp16(sa + pa_off0, ga);
        cp16(sa + pa_off1, ga + 8);
        cp16(sb + pa_off0, gb);
        cp16(sb + pa_off1, gb + 8);
    };

    load_stage(0); CP_COMMIT();
    load_stage(1); CP_COMMIT();

    for (int j = 0; j < niter; ++j) {
        CP_WAIT(1);
        __syncthreads();
        if (j + 2 < niter) load_stage(j + 2);
        CP_COMMIT();

        const uint32_t sa = sbase + (uint32_t)(j % 3) * STAGE;
        const uint32_t sb = sa + TILE;

        // load B fragments for BOTH k-steps (kept resident: 32 regs)
        uint32_t b0[4][4], b1[4][4];
#pragma unroll
        for (int p = 0; p < 4; p++) ldm4(b0[p], sb + b_off[p]);
#pragma unroll
        for (int p = 0; p < 4; p++) ldm4(b1[p], sb + (b_off[p] ^ 32u));

#pragma unroll
        for (int mt = 0; mt < 2; mt++) {
            uint32_t a0[4], a1[4];
            ldm4(a0, sa + a_off[mt]);
            ldm4(a1, sa + (a_off[mt] ^ 32u));
#pragma unroll
            for (int p = 0; p < 4; p++) {
                // fp16-accumulate across the K=32 chunk (2 HMMAs per nt)
                uint32_t c0[2] = {0u, 0u}, c1[2] = {0u, 0u};
                mma16816h(c0, a0, b0[p][0], b0[p][2]);
                mma16816h(c1, a0, b0[p][1], b0[p][3]);
                mma16816h(c0, a1, b1[p][0], b1[p][2]);
                mma16816h(c1, a1, b1[p][1], b1[p][3]);
                // promote to fp32 master accumulators
                float2 f;
                f = __half22float2(*reinterpret_cast<__half2*>(&c0[0]));
                acc[mt][2 * p][0] += f.x;  acc[mt][2 * p][1] += f.y;
                f = __half22float2(*reinterpret_cast<__half2*>(&c0[1]));
                acc[mt][2 * p][2] += f.x;  acc[mt][2 * p][3] += f.y;
                f = __half22float2(*reinterpret_cast<__half2*>(&c1[0]));
                acc[mt][2 * p + 1][0] += f.x;  acc[mt][2 * p + 1][1] += f.y;
                f = __half22float2(*reinterpret_cast<__half2*>(&c1[1]));
                acc[mt][2 * p + 1][2] += f.x;  acc[mt][2 * p + 1][3] += f.y;
            }
        }
    }

    // epilogue: (v00,v01) = (gate_j, up_j) for col pair -> h fp16
    const int gid  = lane >> 2;
    const int tid4 = lane & 3;
    const int hw = N >> 1;   // = I_DIM
#pragma unroll
    for (int mt = 0; mt < 2; mt++) {
        const int r0 = bm + wm * 32 + mt * 16 + gid;
        const int r1 = r0 + 8;
#pragma unroll
        for (int nt = 0; nt < 8; nt++) {
            const int col = bn + wn * 64 + nt * 8 + tid4 * 2;
            const int jj = col >> 1;
            float v00 = acc[mt][nt][0], v01 = acc[mt][nt][1];
            float v10 = acc[mt][nt][2], v11 = acc[mt][nt][3];
            float h0 = v00 / (1.f + expf(-v00)) * v01;
            float h1 = v10 / (1.f + expf(-v10)) * v11;
            Hh[(size_t)r0 * hw + jj] = __float2half_rn(h0);
            Hh[(size_t)r1 * hw + jj] = __float2half_rn(h1);
        }
    }
}

// ---------------- BatchNorm stats, coalesced two-phase ----------------
__global__ void __launch_bounds__(256)
bn_partial(const float4* __restrict__ gxy4, float* __restrict__ part)
{
    const int b = blockIdx.x, tid = threadIdx.x;
    const int col = tid & 63;
    const int rp  = tid >> 6;
    float4 s = make_float4(0.f, 0.f, 0.f, 0.f);
    float4 q = make_float4(0.f, 0.f, 0.f, 0.f);
    const int base = b * 64;
#pragma unroll
    for (int p = 0; p < 16; p++) {
        float4 v = gxy4[(size_t)(base + p * 4 + rp) * 64 + col];
        s.x += v.x; s.y += v.y; s.z += v.z; s.w += v.w;
        q.x += v.x * v.x; q.y += v.y * v.y; q.z += v.z * v.z; q.w += v.w * v.w;
    }
    __shared__ float4 ss[256], qq[256];
    ss[tid] = s; qq[tid] = q;
    __syncthreads();
    if (tid < 64) {
        float4 S = ss[tid], Q = qq[tid];
#pragma unroll
        for (int k = 1; k < 4; k++) {
            float4 a = ss[tid + 64 * k], c = qq[tid + 64 * k];
            S.x += a.x; S.y += a.y; S.z += a.z; S.w += a.w;
            Q.x += c.x; Q.y += c.y; Q.z += c.z; Q.w += c.w;
        }
        ((float4*)(part + (size_t)b * 512))[tid]       = S;
        ((float4*)(part + (size_t)b * 512 + 256))[tid] = Q;
    }
}

__global__ void __launch_bounds__(256)
bn_final(const float* __restrict__ part, float* __restrict__ bn)
{
    const int fb = threadIdx.x;
    float s = 0.f, q = 0.f;
    for (int b = 0; b < 128; b++) {
        s += part[(size_t)b * 512 + fb];
        q += part[(size_t)b * 512 + 256 + fb];
    }
    float mean = s / (float)T_TOK;
    float var  = q / (float)T_TOK - mean * mean;
    const int f = fb & (S_DIM - 1);
    const int base = (fb < S_DIM) ? 0 : 2;
    bn[base * S_DIM + f]       = mean;
    bn[(base + 1) * S_DIM + f] = rsqrtf(var + 1e-5f);
}

// ---------------- Router: one warp per token ----------------
#define NEG_BIG (-1e30f)
__global__ void __launch_bounds__(128)
router_warp(const float* __restrict__ gxy, const float* __restrict__ bn,
            int* __restrict__ ti, float* __restrict__ tw)
{
    const int w = threadIdx.x >> 5, l = threadIdx.x & 31;
    const int t = blockIdx.x * 4 + w;

    __shared__ float s_tvx[4][16], s_tvy[4][16];
    __shared__ int   s_tix[4][16], s_tiy[4][16];

    const float4 mux = ((const float4*)bn)[l];
    const float4 ivx = ((const float4*)bn)[32 + l];
    const float4 muy = ((const float4*)bn)[64 + l];
    const float4 ivy = ((const float4*)bn)[96 + l];

    float4 vx = ((const float4*)(gxy + (size_t)t * 256))[l];
    float4 vy = ((const float4*)(gxy + (size_t)t * 256))[32 + l];
    vx.x = (vx.x - mux.x) * ivx.x; vx.y = (vx.y - mux.y) * ivx.y;
    vx.z = (vx.z - mux.z) * ivx.z; vx.w = (vx.w - mux.w) * ivx.w;
    vy.x = (vy.x - muy.x) * ivy.x; vy.y = (vy.y - muy.y) * ivy.y;
    vy.z = (vy.z - muy.z) * ivy.z; vy.w = (vy.w - muy.w) * ivy.w;

    float m = fmaxf(fmaxf(vx.x, vx.y), fmaxf(vx.z, vx.w));
    for (int o = 16; o; o >>= 1) m = fmaxf(m, __shfl_xor_sync(~0u, m, o));
    float se = expf(vx.x - m) + expf(vx.y - m) + expf(vx.z - m) + expf(vx.w - m);
    for (int o = 16; o; o >>= 1) se += __shfl_xor_sync(~0u, se, o);
    float ls = m + logf(se);
    float a0 = vx.x - ls, a1 = vx.y - ls, a2 = vx.z - ls, a3 = vx.w - ls;

    m = fmaxf(fmaxf(vy.x, vy.y), fmaxf(vy.z, vy.w));
    for (int o = 16; o; o >>= 1) m = fmaxf(m, __shfl_xor_sync(~0u, m, o));
    se = expf(vy.x - m) + expf(vy.y - m) + expf(vy.z - m) + expf(vy.w - m);
    for (int o = 16; o; o >>= 1) se += __shfl_xor_sync(~0u, se, o);
    ls = m + logf(se);
    float b0 = vy.x - ls, b1 = vy.y - ls, b2 = vy.z - ls, b3 = vy.w - ls;

    for (int r = 0; r < TOPK; r++) {
        float v = a0; int ii = 0;
        if (a1 > v) { v = a1; ii = 1; }
        if (a2 > v) { v = a2; ii = 2; }
        if (a3 > v) { v = a3; ii = 3; }
        int idx = (l << 2) | ii;
        for (int o = 16; o; o >>= 1) {
            float ov = __shfl_xor_sync(~0u, v, o);
            int   oi = __shfl_xor_sync(~0u, idx, o);
            if (ov > v || (ov == v && oi < idx)) { v = ov; idx = oi; }
        }
        if (l == 0) { s_tvx[w][r] = v; s_tix[w][r] = idx; }
        if ((idx >> 2) == l) {
            int q = idx & 3;
            if (q == 0) a0 = NEG_BIG; else if (q == 1) a1 = NEG_BIG;
            else if (q == 2) a2 = NEG_BIG; else a3 = NEG_BIG;
        }
    }
    for (int r = 0; r < TOPK; r++) {
        float v = b0; int ii = 0;
        if (b1 > v) { v = b1; ii = 1; }
        if (b2 > v) { v = b2; ii = 2; }
        if (b3 > v) { v = b3; ii = 3; }
        int idx = (l << 2) | ii;
        for (int o = 16; o; o >>= 1) {
            float ov = __shfl_xor_sync(~0u, v, o);
            int   oi = __shfl_xor_sync(~0u, idx, o);
            if (ov > v || (ov == v && oi < idx)) { v = ov; idx = oi; }
        }
        if (l == 0) { s_tvy[w][r] = v; s_tiy[w][r] = idx; }
        if ((idx >> 2) == l) {
            int q = idx & 3;
            if (q == 0) b0 = NEG_BIG; else if (q == 1) b1 = NEG_BIG;
            else if (q == 2) b2 = NEG_BIG; else b3 = NEG_BIG;
        }
    }
    __syncwarp();

    float cd[8];
#pragma unroll
    for (int j = 0; j < 8; j++) {
        int c = l * 8 + j;
        cd[j] = s_tvx[w][c >> 4] + s_tvy[w][c & 15];
    }
    for (int r = 0; r < TOPK; r++) {
        float v = cd[0]; int ii = 0;
#pragma unroll
        for (int j = 1; j < 8; j++) if (cd[j] > v) { v = cd[j]; ii = j; }
        int idx = (l << 3) | ii;
        for (int o = 16; o; o >>= 1) {
            float ov = __shfl_xor_sync(~0u, v, o);
            int   oi = __shfl_xor_sync(~0u, idx, o);
            if (ov > v || (ov == v && oi < idx)) { v = ov; idx = oi; }
        }
        if ((idx >> 3) == l) {
            int q = idx & 7;
#pragma unroll
            for (int j = 0; j < 8; j++) if (j == q) cd[j] = NEG_BIG;
        }
        if (l == 0) {
            int a = idx >> 4, b = idx & 15;
            ti[t * TOPK + r] = s_tix[w][a] * S_DIM + s_tiy[w][b];
            tw[t * TOPK + r] = expf(v);
        }
    }
}

// ---------------- Expert v4: 128 threads, fp16 tables + fp16 x ----------------
__global__ void __launch_bounds__(128)
expert_v4(const __half* __restrict__ xh, const __half* __restrict__ ue,
          const __half* __restrict__ de,
          const int* __restrict__ ti, const float* __restrict__ tw,
          float* __restrict__ out)
{
    const int t = blockIdx.x, tid = threadIdx.x;
    const int w = tid >> 5, l = tid & 31;

    __shared__ __half2 xs[H_DIM / 2];
    __shared__ float   acc_s[4][H_DIM];

#pragma unroll
    for (int i = 0; i < 4; i++)
        xs[tid + i * 128] = ((const __half2*)(xh + (size_t)t * H_DIM))[tid + i * 128];
    __syncthreads();

    float4 acc[8];
#pragma unroll
    for (int i = 0; i < 8; i++) acc[i] = make_float4(0.f, 0.f, 0.f, 0.f);

#pragma unroll
    for (int half = 0; half < 4; half++) {
        const int kk = w + half * 4;
        const int e = ti[t * TOPK + kk];
        const __half* ur = ue + (size_t)e * H_DIM;
        float p = 0.f;
#pragma unroll
        for (int i = 0; i < 8; i++) {
            const int f4 = i * 32 + l;
            uint2 raw = *(const uint2*)(ur + f4 * 4);
            __half2 u01 = *reinterpret_cast<const __half2*>(&raw.x);
            __half2 u23 = *reinterpret_cast<const __half2*>(&raw.y);
            float2 a = __half22float2(u01), b = __half22float2(u23);
            float2 x0 = __half22float2(xs[2 * f4]);
            float2 x1 = __half22float2(xs[2 * f4 + 1]);
            p += a.x * x0.x + a.y * x0.y + b.x * x1.x + b.y * x1.y;
        }
#pragma unroll
        for (int o = 16; o; o >>= 1) p += __shfl_xor_sync(~0u, p, o);
        const float coef = tw[t * TOPK + kk] * p;
        const __half* dr = de + (size_t)e * H_DIM;
#pragma unroll
        for (int i = 0; i < 8; i++) {
            const int f4 = i * 32 + l;
            uint2 raw = *(const uint2*)(dr + f4 * 4);
            __half2 d01 = *reinterpret_cast<const __half2*>(&raw.x);
            __half2 d23 = *reinterpret_cast<const __half2*>(&raw.y);
            float2 a = __half22float2(d01), b = __half22float2(d23);
            acc[i].x += coef * a.x; acc[i].y += coef * a.y;
            acc[i].z += coef * b.x; acc[i].w += coef * b.y;
        }
    }
    float4* as = (float4*)acc_s[w];
#pragma unroll
    for (int i = 0; i < 8; i++) as[i * 32 + l] = acc[i];
    __syncthreads();

#pragma unroll
    for (int i = 0; i < 2; i++) {
        const int j = tid + i * 128;
        float4 r = ((const float4*)acc_s[0])[j];
#pragma unroll
        for (int w2 = 1; w2 < 4; w2++) {
            float4 v = ((const float4*)acc_s[w2])[j];
            r.x += v.x; r.y += v.y; r.z += v.z; r.w += v.w;
        }
        ((float4*)(out + (size_t)t * H_DIM))[j] = r;
    }
}

// ---------------- launch (two-stream, graph-capturable) ----------------
extern "C" void kernel_launch(void* const* d_in, const int* in_sizes, int n_in,
                              void* d_out, int out_size)
{
    const float* x   = (const float*)d_in[0];
    const float* wg  = (const float*)d_in[1];
    const float* wu  = (const float*)d_in[2];
    const float* wd  = (const float*)d_in[3];
    const float* wrx = (const float*)d_in[4];
    const float* wry = (const float*)d_in[5];
    const float* ue  = (const float*)d_in[6];
    const float* de  = (const float*)d_in[7];
    float* out = (float*)d_out;

    __half *xh, *wgu, *wdh, *wrh, *ueh, *deh, *hh;
    float *gxy, *bnp, *bn, *tw;
    int* ti;
    cudaGetSymbolAddress((void**)&xh, g_xh);
    cudaGetSymbolAddress((void**)&wgu, g_wgu);
    cudaGetSymbolAddress((void**)&wdh, g_wdh);
    cudaGetSymbolAddress((void**)&wrh, g_wrh);
    cudaGetSymbolAddress((void**)&ueh, g_ueh);
    cudaGetSymbolAddress((void**)&deh, g_deh);
    cudaGetSymbolAddress((void**)&hh, g_hh);
    cudaGetSymbolAddress((void**)&gxy, g_gxy);
    cudaGetSymbolAddress((void**)&bnp, g_bnp);
    cudaGetSymbolAddress((void**)&bn, g_bn);
    cudaGetSymbolAddress((void**)&ti, g_ti);
    cudaGetSymbolAddress((void**)&tw, g_tw);

    static cudaStream_t s2 = nullptr;
    static cudaEvent_t ev0 = nullptr, ev1 = nullptr, ev_join = nullptr;
    if (!s2) {
        cudaStreamCreateWithFlags(&s2, cudaStreamNonBlocking);
        cudaEventCreateWithFlags(&ev0, cudaEventDisableTiming);
        cudaEventCreateWithFlags(&ev1, cudaEventDisableTiming);
        cudaEventCreateWithFlags(&ev_join, cudaEventDisableTiming);
    }

    constexpr int SMEM = 3 * 2 * 128 * 64;  // 48 KB, occ 2
    const int SH = S_DIM * H_DIM;

    // fork 0: side stream conversions start immediately (wd moved here)
    cudaEventRecord(ev0, 0);
    cudaStreamWaitEvent(s2, ev0, 0);
    conv_half<<<2048, 256, 0, s2>>>((const float4*)wd, (__half2*)wdh, H_DIM * I_DIM / 4);
    conv_half<<<2048, 256, 0, s2>>>((const float4*)ue, (__half2*)ueh, E_NUM * H_DIM / 4);
    conv_half<<<2048, 256, 0, s2>>>((const float4*)de, (__half2*)deh, E_NUM * H_DIM / 4);
    conv_half<<<128, 256, 0, s2>>>((const float4*)wrx, (__half2*)wrh, SH / 4);
    conv_half<<<128, 256, 0, s2>>>((const float4*)wry, (__half2*)(wrh + SH), SH / 4);

    // main: conv x + interleave, then fork 1
    conv_half<<<2048, 256>>>((const float4*)x, (__half2*)xh, T_TOK * H_DIM / 4);
    conv_interleave<<<2048, 256>>>((const float4*)wg, (const float4*)wu,
                                   (__half2*)wgu, I_DIM * H_DIM / 4);
    cudaEventRecord(ev1, 0);

    // side: router chain + expert branch
    cudaStreamWaitEvent(s2, ev1, 0);
    gemm_mma<0><<<dim3(2, T_TOK / 128), 256, SMEM, s2>>>(
        xh, wrh, H_DIM, H_DIM / 32, 2 * S_DIM, gxy);
    bn_partial<<<128, 256, 0, s2>>>((const float4*)gxy, bnp);
    bn_final<<<1, 256, 0, s2>>>(bnp, bn);
    router_warp<<<T_TOK / 4, 128, 0, s2>>>(gxy, bn, ti, tw);
    expert_v4<<<T_TOK, 128, 0, s2>>>(xh, ueh, deh, ti, tw, out);
    cudaEventRecord(ev_join, s2);

    // main: fused gate+up with fp16-accumulate HMMA
    gemm_gateup_h<<<dim3(2 * I_DIM / 128, T_TOK / 128), 256, SMEM>>>(
        xh, wgu, H_DIM, H_DIM / 32, 2 * I_DIM, hh);

    // join: down GEMM (fp32-acc) accumulates onto expert output
    cudaStreamWaitEvent(0, ev_join, 0);
    gemm_mma<2><<<dim3(H_DIM / 128, T_TOK / 128), 256, SMEM>>>(
        hh, wdh, I_DIM, I_DIM / 32, H_DIM, out);
}

// round 14
// speedup vs baseline: 1.1730x; 1.1730x over previous
#include <cuda_runtime.h>
#include <cuda_fp16.h>
#include <math.h>
#include <stdint.h>

#define T_TOK 8192
#define H_DIM 1024
#define I_DIM 4096
#define S_DIM 128
#define E_NUM 16384
#define TOPK  16

// ---------------- scratch ----------------
__device__ __align__(16) __half g_xh  [(size_t)T_TOK * H_DIM];
__device__ __align__(16) __half g_wgu [(size_t)2 * I_DIM * H_DIM];   // interleaved [wg_j; wu_j]
__device__ __align__(16) __half g_wdh [(size_t)H_DIM * I_DIM];
__device__ __align__(16) __half g_wrh [(size_t)2 * S_DIM * H_DIM];   // [wrx; wry]
__device__ __align__(16) __half g_ueh [(size_t)E_NUM * H_DIM];
__device__ __align__(16) __half g_deh [(size_t)E_NUM * H_DIM];
__device__ __align__(16) __half g_hh  [(size_t)T_TOK * I_DIM];
__device__ __align__(16) float  g_gxy [(size_t)T_TOK * 2 * S_DIM];   // [T, 256]
__device__ __align__(16) float  g_bnp [128 * 512];
__device__ __align__(16) float  g_bn  [4 * S_DIM];
__device__ __align__(16) int    g_ti  [(size_t)T_TOK * TOPK];
__device__ __align__(16) float  g_tw  [(size_t)T_TOK * TOPK];

// ---------------- PTX helpers (sm_80-compatible only) ----------------
__device__ __forceinline__ uint32_t s2u(const void* p) {
    uint32_t a;
    asm("{ .reg .u64 t; cvta.to.shared.u64 t, %1; cvt.u32.u64 %0, t; }" : "=r"(a) : "l"(p));
    return a;
}
__device__ __forceinline__ void cp16(uint32_t dst, const void* src) {
    asm volatile("cp.async.cg.shared.global [%0], [%1], 16;" :: "r"(dst), "l"(src));
}
#define CP_COMMIT() asm volatile("cp.async.commit_group;" ::: "memory")
#define CP_WAIT(N)  asm volatile("cp.async.wait_group %0;" :: "n"(N) : "memory")

__device__ __forceinline__ void ldm4(uint32_t* r, uint32_t addr) {
    asm volatile("ldmatrix.sync.aligned.m8n8.x4.shared.b16 {%0,%1,%2,%3}, [%4];"
                 : "=r"(r[0]), "=r"(r[1]), "=r"(r[2]), "=r"(r[3]) : "r"(addr));
}
__device__ __forceinline__ void mma16816(float* c, const uint32_t* a, uint32_t b0, uint32_t b1) {
    asm volatile("mma.sync.aligned.m16n8k16.row.col.f32.f16.f16.f32 "
                 "{%0,%1,%2,%3}, {%4,%5,%6,%7}, {%8,%9}, {%0,%1,%2,%3};"
                 : "+f"(c[0]), "+f"(c[1]), "+f"(c[2]), "+f"(c[3])
                 : "r"(a[0]), "r"(a[1]), "r"(a[2]), "r"(a[3]), "r"(b0), "r"(b1));
}

// smem tile: 128 rows x 32 f16 (64B/row); chunk = 16B of 8 f16.
// swizzle: chunk' = chunk ^ ((row>>1)&3)
__device__ __forceinline__ uint32_t tile_off(int row, int chunk) {
    return (uint32_t)row * 64u + (uint32_t)((chunk ^ ((row >> 1) & 3)) * 16);
}

// ---------------- fp32 -> fp16 (2x ILP) ----------------
__global__ void conv_half(const float4* __restrict__ in, __half2* __restrict__ o, int n4)
{
    const int stride = gridDim.x * blockDim.x;
    int i = blockIdx.x * blockDim.x + threadIdx.x;
    for (; i + stride < n4; i += 2 * stride) {
        float4 v0 = in[i];
        float4 v1 = in[i + stride];
        o[2 * i]     = __half2{__float2half_rn(v0.x), __float2half_rn(v0.y)};
        o[2 * i + 1] = __half2{__float2half_rn(v0.z), __float2half_rn(v0.w)};
        o[2 * (i + stride)]     = __half2{__float2half_rn(v1.x), __float2half_rn(v1.y)};
        o[2 * (i + stride) + 1] = __half2{__float2half_rn(v1.z), __float2half_rn(v1.w)};
    }
    if (i < n4) {
        float4 v = in[i];
        o[2 * i]     = __half2{__float2half_rn(v.x), __float2half_rn(v.y)};
        o[2 * i + 1] = __half2{__float2half_rn(v.z), __float2half_rn(v.w)};
    }
}

// interleave wg/wu rows: W'[2j] = wg[j], W'[2j+1] = wu[j]  (fp32 -> fp16)
__global__ void conv_interleave(const float4* __restrict__ wg, const float4* __restrict__ wu,
                                __half2* __restrict__ o, int n4)   // n4 = I*H/4
{
    constexpr int H4 = H_DIM / 4;
    for (int i = blockIdx.x * blockDim.x + threadIdx.x; i < n4; i += gridDim.x * blockDim.x) {
        int row = i / H4, c = i % H4;
        float4 g = wg[i], u = wu[i];
        size_t dg = (size_t)(2 * row) * H4 + c;
        size_t du = (size_t)(2 * row + 1) * H4 + c;
        o[2 * dg]     = __half2{__float2half_rn(g.x), __float2half_rn(g.y)};
        o[2 * dg + 1] = __half2{__float2half_rn(g.z), __float2half_rn(g.w)};
        o[2 * du]     = __half2{__float2half_rn(u.x), __float2half_rn(u.y)};
        o[2 * du + 1] = __half2{__float2half_rn(u.z), __float2half_rn(u.w)};
    }
}

// ---------------------------------------------------------------------------
// fp16 single-pass GEMM, fp32 accumulate — measured-best config (R12).
// EPI: 0 = C = D;  2 = C += D;
//      3 = interleaved gate/up: col pair (2j,2j+1) -> h_j = silu(D_2j)*D_2j+1 -> Hh fp16
// ---------------------------------------------------------------------------
template<int EPI>
__global__ void __launch_bounds__(256, 2)
gemm_mma(const __half* __restrict__ A, const __half* __restrict__ B,
         int K, int niter, int N,
         float* __restrict__ C, __half* __restrict__ Hh)
{
    constexpr uint32_t TILE = 128 * 64;
    constexpr uint32_t STAGE = 2 * TILE;
    extern __shared__ char smem[];
    const uint32_t sbase = s2u(smem);

    const int tid  = threadIdx.x;
    const int lane = tid & 31;
    const int wid  = tid >> 5;
    const int wm   = wid >> 1;
    const int wn   = wid & 1;
    const int bm   = blockIdx.y * 128;
    const int bn   = blockIdx.x * 128;

    const int prow = tid >> 1;
    const int pc0  = (tid & 1) * 2;
    const uint32_t pa_off0 = tile_off(prow, pc0);
    const uint32_t pa_off1 = tile_off(prow, pc0 + 1);

    const int lrow8 = ((lane >> 3) & 1) * 8 + (lane & 7);
    const int lchnk = lane >> 4;
    uint32_t a_off[2], b_off[4];
#pragma unroll
    for (int mt = 0; mt < 2; mt++)
        a_off[mt] = tile_off(wm * 32 + mt * 16 + lrow8, lchnk);
#pragma unroll
    for (int p = 0; p < 4; p++)
        b_off[p] = tile_off(wn * 64 + p * 16 + lrow8, lchnk);

    float acc[2][8][4];
#pragma unroll
    for (int mt = 0; mt < 2; mt++)
#pragma unroll
        for (int nt = 0; nt < 8; nt++)
#pragma unroll
            for (int q = 0; q < 4; q++) acc[mt][nt][q] = 0.f;

    auto load_stage = [&](int j) {
        const int kk = j * 32;
        const uint32_t sa = sbase + (uint32_t)(j % 3) * STAGE;
        const uint32_t sb = sa + TILE;
        const __half* ga = A + (size_t)(bm + prow) * K + kk + pc0 * 8;
        const __half* gb = B + (size_t)(bn + prow) * K + kk + pc0 * 8;
        cp16(sa + pa_off0, ga);
        cp16(sa + pa_off1, ga + 8);
        cp16(sb + pa_off0, gb);
        cp16(sb + pa_off1, gb + 8);
    };

    load_stage(0); CP_COMMIT();
    load_stage(1); CP_COMMIT();

    for (int j = 0; j < niter; ++j) {
        CP_WAIT(1);
        __syncthreads();
        if (j + 2 < niter) load_stage(j + 2);
        CP_COMMIT();

        const uint32_t sa = sbase + (uint32_t)(j % 3) * STAGE;
        const uint32_t sb = sa + TILE;
#pragma unroll
        for (int ks = 0; ks < 2; ks++) {
            const uint32_t kx = ks ? 32u : 0u;
            uint32_t a[2][4], b[4][4];
#pragma unroll
            for (int mt = 0; mt < 2; mt++) ldm4(a[mt], sa + (a_off[mt] ^ kx));
#pragma unroll
            for (int p = 0; p < 4; p++)    ldm4(b[p], sb + (b_off[p] ^ kx));
#pragma unroll
            for (int mt = 0; mt < 2; mt++)
#pragma unroll
                for (int p = 0; p < 4; p++) {
                    mma16816(acc[mt][2 * p],     a[mt], b[p][0], b[p][2]);
                    mma16816(acc[mt][2 * p + 1], a[mt], b[p][1], b[p][3]);
                }
        }
    }

    const int gid  = lane >> 2;
    const int tid4 = lane & 3;
#pragma unroll
    for (int mt = 0; mt < 2; mt++) {
        const int r0 = bm + wm * 32 + mt * 16 + gid;
        const int r1 = r0 + 8;
#pragma unroll
        for (int nt = 0; nt < 8; nt++) {
            const int col = bn + wn * 64 + nt * 8 + tid4 * 2;
            float v00 = acc[mt][nt][0], v01 = acc[mt][nt][1];
            float v10 = acc[mt][nt][2], v11 = acc[mt][nt][3];
            if (EPI == 0) {
                *(float2*)(C + (size_t)r0 * N + col) = make_float2(v00, v01);
                *(float2*)(C + (size_t)r1 * N + col) = make_float2(v10, v11);
            } else if (EPI == 2) {
                float2 c0 = *(float2*)(C + (size_t)r0 * N + col);
                float2 c1 = *(float2*)(C + (size_t)r1 * N + col);
                *(float2*)(C + (size_t)r0 * N + col) = make_float2(c0.x + v00, c0.y + v01);
                *(float2*)(C + (size_t)r1 * N + col) = make_float2(c1.x + v10, c1.y + v11);
            } else {
                const int hw = N >> 1;
                const int jj = col >> 1;
                float h0 = v00 / (1.f + expf(-v00)) * v01;
                float h1 = v10 / (1.f + expf(-v10)) * v11;
                Hh[(size_t)r0 * hw + jj] = __float2half_rn(h0);
                Hh[(size_t)r1 * hw + jj] = __float2half_rn(h1);
            }
        }
    }
}

// ---------------- BatchNorm stats, coalesced two-phase ----------------
__global__ void __launch_bounds__(256)
bn_partial(const float4* __restrict__ gxy4, float* __restrict__ part)
{
    const int b = blockIdx.x, tid = threadIdx.x;
    const int col = tid & 63;
    const int rp  = tid >> 6;
    float4 s = make_float4(0.f, 0.f, 0.f, 0.f);
    float4 q = make_float4(0.f, 0.f, 0.f, 0.f);
    const int base = b * 64;
#pragma unroll
    for (int p = 0; p < 16; p++) {
        float4 v = gxy4[(size_t)(base + p * 4 + rp) * 64 + col];
        s.x += v.x; s.y += v.y; s.z += v.z; s.w += v.w;
        q.x += v.x * v.x; q.y += v.y * v.y; q.z += v.z * v.z; q.w += v.w * v.w;
    }
    __shared__ float4 ss[256], qq[256];
    ss[tid] = s; qq[tid] = q;
    __syncthreads();
    if (tid < 64) {
        float4 S = ss[tid], Q = qq[tid];
#pragma unroll
        for (int k = 1; k < 4; k++) {
            float4 a = ss[tid + 64 * k], c = qq[tid + 64 * k];
            S.x += a.x; S.y += a.y; S.z += a.z; S.w += a.w;
            Q.x += c.x; Q.y += c.y; Q.z += c.z; Q.w += c.w;
        }
        ((float4*)(part + (size_t)b * 512))[tid]       = S;
        ((float4*)(part + (size_t)b * 512 + 256))[tid] = Q;
    }
}

__global__ void __launch_bounds__(256)
bn_final(const float* __restrict__ part, float* __restrict__ bn)
{
    const int fb = threadIdx.x;
    float s = 0.f, q = 0.f;
    for (int b = 0; b < 128; b++) {
        s += part[(size_t)b * 512 + fb];
        q += part[(size_t)b * 512 + 256 + fb];
    }
    float mean = s / (float)T_TOK;
    float var  = q / (float)T_TOK - mean * mean;
    const int f = fb & (S_DIM - 1);
    const int base = (fb < S_DIM) ? 0 : 2;
    bn[base * S_DIM + f]       = mean;
    bn[(base + 1) * S_DIM + f] = rsqrtf(var + 1e-5f);
}

// ---------------- Router: one warp per token ----------------
#define NEG_BIG (-1e30f)
__global__ void __launch_bounds__(128)
router_warp(const float* __restrict__ gxy, const float* __restrict__ bn,
            int* __restrict__ ti, float* __restrict__ tw)
{
    const int w = threadIdx.x >> 5, l = threadIdx.x & 31;
    const int t = blockIdx.x * 4 + w;

    __shared__ float s_tvx[4][16], s_tvy[4][16];
    __shared__ int   s_tix[4][16], s_tiy[4][16];

    const float4 mux = ((const float4*)bn)[l];
    const float4 ivx = ((const float4*)bn)[32 + l];
    const float4 muy = ((const float4*)bn)[64 + l];
    const float4 ivy = ((const float4*)bn)[96 + l];

    float4 vx = ((const float4*)(gxy + (size_t)t * 256))[l];
    float4 vy = ((const float4*)(gxy + (size_t)t * 256))[32 + l];
    vx.x = (vx.x - mux.x) * ivx.x; vx.y = (vx.y - mux.y) * ivx.y;
    vx.z = (vx.z - mux.z) * ivx.z; vx.w = (vx.w - mux.w) * ivx.w;
    vy.x = (vy.x - muy.x) * ivy.x; vy.y = (vy.y - muy.y) * ivy.y;
    vy.z = (vy.z - muy.z) * ivy.z; vy.w = (vy.w - muy.w) * ivy.w;

    float m = fmaxf(fmaxf(vx.x, vx.y), fmaxf(vx.z, vx.w));
    for (int o = 16; o; o >>= 1) m = fmaxf(m, __shfl_xor_sync(~0u, m, o));
    float se = expf(vx.x - m) + expf(vx.y - m) + expf(vx.z - m) + expf(vx.w - m);
    for (int o = 16; o; o >>= 1) se += __shfl_xor_sync(~0u, se, o);
    float ls = m + logf(se);
    float a0 = vx.x - ls, a1 = vx.y - ls, a2 = vx.z - ls, a3 = vx.w - ls;

    m = fmaxf(fmaxf(vy.x, vy.y), fmaxf(vy.z, vy.w));
    for (int o = 16; o; o >>= 1) m = fmaxf(m, __shfl_xor_sync(~0u, m, o));
    se = expf(vy.x - m) + expf(vy.y - m) + expf(vy.z - m) + expf(vy.w - m);
    for (int o = 16; o; o >>= 1) se += __shfl_xor_sync(~0u, se, o);
    ls = m + logf(se);
    float b0 = vy.x - ls, b1 = vy.y - ls, b2 = vy.z - ls, b3 = vy.w - ls;

    for (int r = 0; r < TOPK; r++) {
        float v = a0; int ii = 0;
        if (a1 > v) { v = a1; ii = 1; }
        if (a2 > v) { v = a2; ii = 2; }
        if (a3 > v) { v = a3; ii = 3; }
        int idx = (l << 2) | ii;
        for (int o = 16; o; o >>= 1) {
            float ov = __shfl_xor_sync(~0u, v, o);
            int   oi = __shfl_xor_sync(~0u, idx, o);
            if (ov > v || (ov == v && oi < idx)) { v = ov; idx = oi; }
        }
        if (l == 0) { s_tvx[w][r] = v; s_tix[w][r] = idx; }
        if ((idx >> 2) == l) {
            int q = idx & 3;
            if (q == 0) a0 = NEG_BIG; else if (q == 1) a1 = NEG_BIG;
            else if (q == 2) a2 = NEG_BIG; else a3 = NEG_BIG;
        }
    }
    for (int r = 0; r < TOPK; r++) {
        float v = b0; int ii = 0;
        if (b1 > v) { v = b1; ii = 1; }
        if (b2 > v) { v = b2; ii = 2; }
        if (b3 > v) { v = b3; ii = 3; }
        int idx = (l << 2) | ii;
        for (int o = 16; o; o >>= 1) {
            float ov = __shfl_xor_sync(~0u, v, o);
            int   oi = __shfl_xor_sync(~0u, idx, o);
            if (ov > v || (ov == v && oi < idx)) { v = ov; idx = oi; }
        }
        if (l == 0) { s_tvy[w][r] = v; s_tiy[w][r] = idx; }
        if ((idx >> 2) == l) {
            int q = idx & 3;
            if (q == 0) b0 = NEG_BIG; else if (q == 1) b1 = NEG_BIG;
            else if (q == 2) b2 = NEG_BIG; else b3 = NEG_BIG;
        }
    }
    __syncwarp();

    float cd[8];
#pragma unroll
    for (int j = 0; j < 8; j++) {
        int c = l * 8 + j;
        cd[j] = s_tvx[w][c >> 4] + s_tvy[w][c & 15];
    }
    for (int r = 0; r < TOPK; r++) {
        float v = cd[0]; int ii = 0;
#pragma unroll
        for (int j = 1; j < 8; j++) if (cd[j] > v) { v = cd[j]; ii = j; }
        int idx = (l << 3) | ii;
        for (int o = 16; o; o >>= 1) {
            float ov = __shfl_xor_sync(~0u, v, o);
            int   oi = __shfl_xor_sync(~0u, idx, o);
            if (ov > v || (ov == v && oi < idx)) { v = ov; idx = oi; }
        }
        if ((idx >> 3) == l) {
            int q = idx & 7;
#pragma unroll
            for (int j = 0; j < 8; j++) if (j == q) cd[j] = NEG_BIG;
        }
        if (l == 0) {
            int a = idx >> 4, b = idx & 15;
            ti[t * TOPK + r] = s_tix[w][a] * S_DIM + s_tiy[w][b];
            tw[t * TOPK + r] = expf(v);
        }
    }
}

// ---------------- Expert v4: 128 threads, fp16 tables + fp16 x ----------------
__global__ void __launch_bounds__(128)
expert_v4(const __half* __restrict__ xh, const __half* __restrict__ ue,
          const __half* __restrict__ de,
          const int* __restrict__ ti, const float* __restrict__ tw,
          float* __restrict__ out)
{
    const int t = blockIdx.x, tid = threadIdx.x;
    const int w = tid >> 5, l = tid & 31;

    __shared__ __half2 xs[H_DIM / 2];
    __shared__ float   acc_s[4][H_DIM];

#pragma unroll
    for (int i = 0; i < 4; i++)
        xs[tid + i * 128] = ((const __half2*)(xh + (size_t)t * H_DIM))[tid + i * 128];
    __syncthreads();

    float4 acc[8];
#pragma unroll
    for (int i = 0; i < 8; i++) acc[i] = make_float4(0.f, 0.f, 0.f, 0.f);

#pragma unroll
    for (int half = 0; half < 4; half++) {
        const int kk = w + half * 4;
        const int e = ti[t * TOPK + kk];
        const __half* ur = ue + (size_t)e * H_DIM;
        float p = 0.f;
#pragma unroll
        for (int i = 0; i < 8; i++) {
            const int f4 = i * 32 + l;
            uint2 raw = *(const uint2*)(ur + f4 * 4);
            __half2 u01 = *reinterpret_cast<const __half2*>(&raw.x);
            __half2 u23 = *reinterpret_cast<const __half2*>(&raw.y);
            float2 a = __half22float2(u01), b = __half22float2(u23);
            float2 x0 = __half22float2(xs[2 * f4]);
            float2 x1 = __half22float2(xs[2 * f4 + 1]);
            p += a.x * x0.x + a.y * x0.y + b.x * x1.x + b.y * x1.y;
        }
#pragma unroll
        for (int o = 16; o; o >>= 1) p += __shfl_xor_sync(~0u, p, o);
        const float coef = tw[t * TOPK + kk] * p;
        const __half* dr = de + (size_t)e * H_DIM;
#pragma unroll
        for (int i = 0; i < 8; i++) {
            const int f4 = i * 32 + l;
            uint2 raw = *(const uint2*)(dr + f4 * 4);
            __half2 d01 = *reinterpret_cast<const __half2*>(&raw.x);
            __half2 d23 = *reinterpret_cast<const __half2*>(&raw.y);
            float2 a = __half22float2(d01), b = __half22float2(d23);
            acc[i].x += coef * a.x; acc[i].y += coef * a.y;
            acc[i].z += coef * b.x; acc[i].w += coef * b.y;
        }
    }
    float4* as = (float4*)acc_s[w];
#pragma unroll
    for (int i = 0; i < 8; i++) as[i * 32 + l] = acc[i];
    __syncthreads();

#pragma unroll
    for (int i = 0; i < 2; i++) {
        const int j = tid + i * 128;
        float4 r = ((const float4*)acc_s[0])[j];
#pragma unroll
        for (int w2 = 1; w2 < 4; w2++) {
            float4 v = ((const float4*)acc_s[w2])[j];
            r.x += v.x; r.y += v.y; r.z += v.z; r.w += v.w;
        }
        ((float4*)(out + (size_t)t * H_DIM))[j] = r;
    }
}

// ---------------- launch (two-stream, graph-capturable) ----------------
extern "C" void kernel_launch(void* const* d_in, const int* in_sizes, int n_in,
                              void* d_out, int out_size)
{
    const float* x   = (const float*)d_in[0];
    const float* wg  = (const float*)d_in[1];
    const float* wu  = (const float*)d_in[2];
    const float* wd  = (const float*)d_in[3];
    const float* wrx = (const float*)d_in[4];
    const float* wry = (const float*)d_in[5];
    const float* ue  = (const float*)d_in[6];
    const float* de  = (const float*)d_in[7];
    float* out = (float*)d_out;

    __half *xh, *wgu, *wdh, *wrh, *ueh, *deh, *hh;
    float *gxy, *bnp, *bn, *tw;
    int* ti;
    cudaGetSymbolAddress((void**)&xh, g_xh);
    cudaGetSymbolAddress((void**)&wgu, g_wgu);
    cudaGetSymbolAddress((void**)&wdh, g_wdh);
    cudaGetSymbolAddress((void**)&wrh, g_wrh);
    cudaGetSymbolAddress((void**)&ueh, g_ueh);
    cudaGetSymbolAddress((void**)&deh, g_deh);
    cudaGetSymbolAddress((void**)&hh, g_hh);
    cudaGetSymbolAddress((void**)&gxy, g_gxy);
    cudaGetSymbolAddress((void**)&bnp, g_bnp);
    cudaGetSymbolAddress((void**)&bn, g_bn);
    cudaGetSymbolAddress((void**)&ti, g_ti);
    cudaGetSymbolAddress((void**)&tw, g_tw);

    static cudaStream_t s2 = nullptr;
    static cudaEvent_t ev0 = nullptr, ev1 = nullptr, ev_join = nullptr;
    if (!s2) {
        cudaStreamCreateWithFlags(&s2, cudaStreamNonBlocking);
        cudaEventCreateWithFlags(&ev0, cudaEventDisableTiming);
        cudaEventCreateWithFlags(&ev1, cudaEventDisableTiming);
        cudaEventCreateWithFlags(&ev_join, cudaEventDisableTiming);
    }

    constexpr int SMEM = 3 * 2 * 128 * 64;  // 48 KB, occ 2
    const int SH = S_DIM * H_DIM;

    // fork 0: side stream conversions start immediately (wd off the main path)
    cudaEventRecord(ev0, 0);
    cudaStreamWaitEvent(s2, ev0, 0);
    conv_half<<<2048, 256, 0, s2>>>((const float4*)wd, (__half2*)wdh, H_DIM * I_DIM / 4);
    conv_half<<<2048, 256, 0, s2>>>((const float4*)ue, (__half2*)ueh, E_NUM * H_DIM / 4);
    conv_half<<<2048, 256, 0, s2>>>((const float4*)de, (__half2*)deh, E_NUM * H_DIM / 4);
    conv_half<<<128, 256, 0, s2>>>((const float4*)wrx, (__half2*)wrh, SH / 4);
    conv_half<<<128, 256, 0, s2>>>((const float4*)wry, (__half2*)(wrh + SH), SH / 4);

    // main: conv x + interleave, then fork 1
    conv_half<<<2048, 256>>>((const float4*)x, (__half2*)xh, T_TOK * H_DIM / 4);
    conv_interleave<<<2048, 256>>>((const float4*)wg, (const float4*)wu,
                                   (__half2*)wgu, I_DIM * H_DIM / 4);
    cudaEventRecord(ev1, 0);

    // side: router chain + expert branch
    cudaStreamWaitEvent(s2, ev1, 0);
    gemm_mma<0><<<dim3(2, T_TOK / 128), 256, SMEM, s2>>>(
        xh, wrh, H_DIM, H_DIM / 32, 2 * S_DIM, gxy, nullptr);
    bn_partial<<<128, 256, 0, s2>>>((const float4*)gxy, bnp);
    bn_final<<<1, 256, 0, s2>>>(bnp, bn);
    router_warp<<<T_TOK / 4, 128, 0, s2>>>(gxy, bn, ti, tw);
    expert_v4<<<T_TOK, 128, 0, s2>>>(xh, ueh, deh, ti, tw, out);
    cudaEventRecord(ev_join, s2);

    // main: fused gate+up (fp32-acc, EPI=3)
    gemm_mma<3><<<dim3(2 * I_DIM / 128, T_TOK / 128), 256, SMEM>>>(
        xh, wgu, H_DIM, H_DIM / 32, 2 * I_DIM, nullptr, hh);

    // join: down GEMM (fp32-acc) accumulates onto expert output
    cudaStreamWaitEvent(0, ev_join, 0);
    gemm_mma<2><<<dim3(H_DIM / 128, T_TOK / 128), 256, SMEM>>>(
        hh, wdh, I_DIM, I_DIM / 32, H_DIM, out, nullptr);
}

// round 15
// speedup vs baseline: 1.1730x; 1.0000x over previous
#include <cuda_runtime.h>
#include <cuda_fp16.h>
#include <math.h>
#include <stdint.h>

#define T_TOK 8192
#define H_DIM 1024
#define I_DIM 4096
#define S_DIM 128
#define E_NUM 16384
#define TOPK  16

// ---------------- scratch ----------------
__device__ __align__(16) __half g_xh  [(size_t)T_TOK * H_DIM];
__device__ __align__(16) __half g_wgu [(size_t)2 * I_DIM * H_DIM];   // interleaved [wg_j; wu_j]
__device__ __align__(16) __half g_wdh [(size_t)H_DIM * I_DIM];
__device__ __align__(16) __half g_wrh [(size_t)2 * S_DIM * H_DIM];   // [wrx; wry]
__device__ __align__(16) __half g_ueh [(size_t)E_NUM * H_DIM];
__device__ __align__(16) __half g_deh [(size_t)E_NUM * H_DIM];
__device__ __align__(16) __half g_hh  [(size_t)T_TOK * I_DIM];
__device__ __align__(16) float  g_gxy [(size_t)T_TOK * 2 * S_DIM];   // [T, 256]
__device__ __align__(16) float  g_bnp [128 * 512];
__device__ __align__(16) float  g_bn  [4 * S_DIM];
__device__ __align__(16) int    g_ti  [(size_t)T_TOK * TOPK];
__device__ __align__(16) float  g_tw  [(size_t)T_TOK * TOPK];

// ---------------- PTX helpers (sm_80-compatible only) ----------------
__device__ __forceinline__ uint32_t s2u(const void* p) {
    uint32_t a;
    asm("{ .reg .u64 t; cvta.to.shared.u64 t, %1; cvt.u32.u64 %0, t; }" : "=r"(a) : "l"(p));
    return a;
}
__device__ __forceinline__ void cp16(uint32_t dst, const void* src) {
    asm volatile("cp.async.cg.shared.global [%0], [%1], 16;" :: "r"(dst), "l"(src));
}
#define CP_COMMIT() asm volatile("cp.async.commit_group;" ::: "memory")
#define CP_WAIT(N)  asm volatile("cp.async.wait_group %0;" :: "n"(N) : "memory")

__device__ __forceinline__ void ldm4(uint32_t* r, uint32_t addr) {
    asm volatile("ldmatrix.sync.aligned.m8n8.x4.shared.b16 {%0,%1,%2,%3}, [%4];"
                 : "=r"(r[0]), "=r"(r[1]), "=r"(r[2]), "=r"(r[3]) : "r"(addr));
}
__device__ __forceinline__ void mma16816(float* c, const uint32_t* a, uint32_t b0, uint32_t b1) {
    asm volatile("mma.sync.aligned.m16n8k16.row.col.f32.f16.f16.f32 "
                 "{%0,%1,%2,%3}, {%4,%5,%6,%7}, {%8,%9}, {%0,%1,%2,%3};"
                 : "+f"(c[0]), "+f"(c[1]), "+f"(c[2]), "+f"(c[3])
                 : "r"(a[0]), "r"(a[1]), "r"(a[2]), "r"(a[3]), "r"(b0), "r"(b1));
}

// smem tile: 128 rows x 32 f16 (64B/row); chunk = 16B of 8 f16.
// swizzle: chunk' = chunk ^ ((row>>1)&3)
__device__ __forceinline__ uint32_t tile_off(int row, int chunk) {
    return (uint32_t)row * 64u + (uint32_t)((chunk ^ ((row >> 1) & 3)) * 16);
}

// ---------------- fp32 -> fp16 (2x ILP) ----------------
__global__ void conv_half(const float4* __restrict__ in, __half2* __restrict__ o, int n4)
{
    const int stride = gridDim.x * blockDim.x;
    int i = blockIdx.x * blockDim.x + threadIdx.x;
    for (; i + stride < n4; i += 2 * stride) {
        float4 v0 = in[i];
        float4 v1 = in[i + stride];
        o[2 * i]     = __half2{__float2half_rn(v0.x), __float2half_rn(v0.y)};
        o[2 * i + 1] = __half2{__float2half_rn(v0.z), __float2half_rn(v0.w)};
        o[2 * (i + stride)]     = __half2{__float2half_rn(v1.x), __float2half_rn(v1.y)};
        o[2 * (i + stride) + 1] = __half2{__float2half_rn(v1.z), __float2half_rn(v1.w)};
    }
    if (i < n4) {
        float4 v = in[i];
        o[2 * i]     = __half2{__float2half_rn(v.x), __float2half_rn(v.y)};
        o[2 * i + 1] = __half2{__float2half_rn(v.z), __float2half_rn(v.w)};
    }
}

// interleave wg/wu rows: W'[2j] = wg[j], W'[2j+1] = wu[j]  (fp32 -> fp16)
__global__ void conv_interleave(const float4* __restrict__ wg, const float4* __restrict__ wu,
                                __half2* __restrict__ o, int n4)   // n4 = I*H/4
{
    constexpr int H4 = H_DIM / 4;
    for (int i = blockIdx.x * blockDim.x + threadIdx.x; i < n4; i += gridDim.x * blockDim.x) {
        int row = i / H4, c = i % H4;
        float4 g = wg[i], u = wu[i];
        size_t dg = (size_t)(2 * row) * H4 + c;
        size_t du = (size_t)(2 * row + 1) * H4 + c;
        o[2 * dg]     = __half2{__float2half_rn(g.x), __float2half_rn(g.y)};
        o[2 * dg + 1] = __half2{__float2half_rn(g.z), __float2half_rn(g.w)};
        o[2 * du]     = __half2{__float2half_rn(u.x), __float2half_rn(u.y)};
        o[2 * du + 1] = __half2{__float2half_rn(u.z), __float2half_rn(u.w)};
    }
}

// ---------------------------------------------------------------------------
// fp16 single-pass GEMM, fp32 accumulate — measured-best config (R12).
// EPI: 0 = C = D;  2 = C += D;
//      3 = interleaved gate/up: col pair (2j,2j+1) -> h_j = silu(D_2j)*D_2j+1 -> Hh fp16
// ---------------------------------------------------------------------------
template<int EPI>
__global__ void __launch_bounds__(256, 2)
gemm_mma(const __half* __restrict__ A, const __half* __restrict__ B,
         int K, int niter, int N,
         float* __restrict__ C, __half* __restrict__ Hh)
{
    constexpr uint32_t TILE = 128 * 64;
    constexpr uint32_t STAGE = 2 * TILE;
    extern __shared__ char smem[];
    const uint32_t sbase = s2u(smem);

    const int tid  = threadIdx.x;
    const int lane = tid & 31;
    const int wid  = tid >> 5;
    const int wm   = wid >> 1;
    const int wn   = wid & 1;
    const int bm   = blockIdx.y * 128;
    const int bn   = blockIdx.x * 128;

    const int prow = tid >> 1;
    const int pc0  = (tid & 1) * 2;
    const uint32_t pa_off0 = tile_off(prow, pc0);
    const uint32_t pa_off1 = tile_off(prow, pc0 + 1);

    const int lrow8 = ((lane >> 3) & 1) * 8 + (lane & 7);
    const int lchnk = lane >> 4;
    uint32_t a_off[2], b_off[4];
#pragma unroll
    for (int mt = 0; mt < 2; mt++)
        a_off[mt] = tile_off(wm * 32 + mt * 16 + lrow8, lchnk);
#pragma unroll
    for (int p = 0; p < 4; p++)
        b_off[p] = tile_off(wn * 64 + p * 16 + lrow8, lchnk);

    float acc[2][8][4];
#pragma unroll
    for (int mt = 0; mt < 2; mt++)
#pragma unroll
        for (int nt = 0; nt < 8; nt++)
#pragma unroll
            for (int q = 0; q < 4; q++) acc[mt][nt][q] = 0.f;

    auto load_stage = [&](int j) {
        const int kk = j * 32;
        const uint32_t sa = sbase + (uint32_t)(j % 3) * STAGE;
        const uint32_t sb = sa + TILE;
        const __half* ga = A + (size_t)(bm + prow) * K + kk + pc0 * 8;
        const __half* gb = B + (size_t)(bn + prow) * K + kk + pc0 * 8;
        cp16(sa + pa_off0, ga);
        cp16(sa + pa_off1, ga + 8);
        cp16(sb + pa_off0, gb);
        cp16(sb + pa_off1, gb + 8);
    };

    load_stage(0); CP_COMMIT();
    load_stage(1); CP_COMMIT();

    for (int j = 0; j < niter; ++j) {
        CP_WAIT(1);
        __syncthreads();
        if (j + 2 < niter) load_stage(j + 2);
        CP_COMMIT();

        const uint32_t sa = sbase + (uint32_t)(j % 3) * STAGE;
        const uint32_t sb = sa + TILE;
#pragma unroll
        for (int ks = 0; ks < 2; ks++) {
            const uint32_t kx = ks ? 32u : 0u;
            uint32_t a[2][4], b[4][4];
#pragma unroll
            for (int mt = 0; mt < 2; mt++) ldm4(a[mt], sa + (a_off[mt] ^ kx));
#pragma unroll
            for (int p = 0; p < 4; p++)    ldm4(b[p], sb + (b_off[p] ^ kx));
#pragma unroll
            for (int mt = 0; mt < 2; mt++)
#pragma unroll
                for (int p = 0; p < 4; p++) {
                    mma16816(acc[mt][2 * p],     a[mt], b[p][0], b[p][2]);
                    mma16816(acc[mt][2 * p + 1], a[mt], b[p][1], b[p][3]);
                }
        }
    }

    const int gid  = lane >> 2;
    const int tid4 = lane & 3;
#pragma unroll
    for (int mt = 0; mt < 2; mt++) {
        const int r0 = bm + wm * 32 + mt * 16 + gid;
        const int r1 = r0 + 8;
#pragma unroll
        for (int nt = 0; nt < 8; nt++) {
            const int col = bn + wn * 64 + nt * 8 + tid4 * 2;
            float v00 = acc[mt][nt][0], v01 = acc[mt][nt][1];
            float v10 = acc[mt][nt][2], v11 = acc[mt][nt][3];
            if (EPI == 0) {
                *(float2*)(C + (size_t)r0 * N + col) = make_float2(v00, v01);
                *(float2*)(C + (size_t)r1 * N + col) = make_float2(v10, v11);
            } else if (EPI == 2) {
                float2 c0 = *(float2*)(C + (size_t)r0 * N + col);
                float2 c1 = *(float2*)(C + (size_t)r1 * N + col);
                *(float2*)(C + (size_t)r0 * N + col) = make_float2(c0.x + v00, c0.y + v01);
                *(float2*)(C + (size_t)r1 * N + col) = make_float2(c1.x + v10, c1.y + v11);
            } else {
                const int hw = N >> 1;
                const int jj = col >> 1;
                float h0 = v00 / (1.f + expf(-v00)) * v01;
                float h1 = v10 / (1.f + expf(-v10)) * v11;
                Hh[(size_t)r0 * hw + jj] = __float2half_rn(h0);
                Hh[(size_t)r1 * hw + jj] = __float2half_rn(h1);
            }
        }
    }
}

// ---------------- BatchNorm stats, coalesced two-phase ----------------
__global__ void __launch_bounds__(256)
bn_partial(const float4* __restrict__ gxy4, float* __restrict__ part)
{
    const int b = blockIdx.x, tid = threadIdx.x;
    const int col = tid & 63;
    const int rp  = tid >> 6;
    float4 s = make_float4(0.f, 0.f, 0.f, 0.f);
    float4 q = make_float4(0.f, 0.f, 0.f, 0.f);
    const int base = b * 64;
#pragma unroll
    for (int p = 0; p < 16; p++) {
        float4 v = gxy4[(size_t)(base + p * 4 + rp) * 64 + col];
        s.x += v.x; s.y += v.y; s.z += v.z; s.w += v.w;
        q.x += v.x * v.x; q.y += v.y * v.y; q.z += v.z * v.z; q.w += v.w * v.w;
    }
    __shared__ float4 ss[256], qq[256];
    ss[tid] = s; qq[tid] = q;
    __syncthreads();
    if (tid < 64) {
        float4 S = ss[tid], Q = qq[tid];
#pragma unroll
        for (int k = 1; k < 4; k++) {
            float4 a = ss[tid + 64 * k], c = qq[tid + 64 * k];
            S.x += a.x; S.y += a.y; S.z += a.z; S.w += a.w;
            Q.x += c.x; Q.y += c.y; Q.z += c.z; Q.w += c.w;
        }
        ((float4*)(part + (size_t)b * 512))[tid]       = S;
        ((float4*)(part + (size_t)b * 512 + 256))[tid] = Q;
    }
}

__global__ void __launch_bounds__(256)
bn_final(const float* __restrict__ part, float* __restrict__ bn)
{
    const int fb = threadIdx.x;
    float s = 0.f, q = 0.f;
    for (int b = 0; b < 128; b++) {
        s += part[(size_t)b * 512 + fb];
        q += part[(size_t)b * 512 + 256 + fb];
    }
    float mean = s / (float)T_TOK;
    float var  = q / (float)T_TOK - mean * mean;
    const int f = fb & (S_DIM - 1);
    const int base = (fb < S_DIM) ? 0 : 2;
    bn[base * S_DIM + f]       = mean;
    bn[(base + 1) * S_DIM + f] = rsqrtf(var + 1e-5f);
}

// ---------------- Router: one warp per token ----------------
#define NEG_BIG (-1e30f)
__global__ void __launch_bounds__(128)
router_warp(const float* __restrict__ gxy, const float* __restrict__ bn,
            int* __restrict__ ti, float* __restrict__ tw)
{
    const int w = threadIdx.x >> 5, l = threadIdx.x & 31;
    const int t = blockIdx.x * 4 + w;

    __shared__ float s_tvx[4][16], s_tvy[4][16];
    __shared__ int   s_tix[4][16], s_tiy[4][16];

    const float4 mux = ((const float4*)bn)[l];
    const float4 ivx = ((const float4*)bn)[32 + l];
    const float4 muy = ((const float4*)bn)[64 + l];
    const float4 ivy = ((const float4*)bn)[96 + l];

    float4 vx = ((const float4*)(gxy + (size_t)t * 256))[l];
    float4 vy = ((const float4*)(gxy + (size_t)t * 256))[32 + l];
    vx.x = (vx.x - mux.x) * ivx.x; vx.y = (vx.y - mux.y) * ivx.y;
    vx.z = (vx.z - mux.z) * ivx.z; vx.w = (vx.w - mux.w) * ivx.w;
    vy.x = (vy.x - muy.x) * ivy.x; vy.y = (vy.y - muy.y) * ivy.y;
    vy.z = (vy.z - muy.z) * ivy.z; vy.w = (vy.w - muy.w) * ivy.w;

    float m = fmaxf(fmaxf(vx.x, vx.y), fmaxf(vx.z, vx.w));
    for (int o = 16; o; o >>= 1) m = fmaxf(m, __shfl_xor_sync(~0u, m, o));
    float se = expf(vx.x - m) + expf(vx.y - m) + expf(vx.z - m) + expf(vx.w - m);
    for (int o = 16; o; o >>= 1) se += __shfl_xor_sync(~0u, se, o);
    float ls = m + logf(se);
    float a0 = vx.x - ls, a1 = vx.y - ls, a2 = vx.z - ls, a3 = vx.w - ls;

    m = fmaxf(fmaxf(vy.x, vy.y), fmaxf(vy.z, vy.w));
    for (int o = 16; o; o >>= 1) m = fmaxf(m, __shfl_xor_sync(~0u, m, o));
    se = expf(vy.x - m) + expf(vy.y - m) + expf(vy.z - m) + expf(vy.w - m);
    for (int o = 16; o; o >>= 1) se += __shfl_xor_sync(~0u, se, o);
    ls = m + logf(se);
    float b0 = vy.x - ls, b1 = vy.y - ls, b2 = vy.z - ls, b3 = vy.w - ls;

    for (int r = 0; r < TOPK; r++) {
        float v = a0; int ii = 0;
        if (a1 > v) { v = a1; ii = 1; }
        if (a2 > v) { v = a2; ii = 2; }
        if (a3 > v) { v = a3; ii = 3; }
        int idx = (l << 2) | ii;
        for (int o = 16; o; o >>= 1) {
            float ov = __shfl_xor_sync(~0u, v, o);
            int   oi = __shfl_xor_sync(~0u, idx, o);
            if (ov > v || (ov == v && oi < idx)) { v = ov; idx = oi; }
        }
        if (l == 0) { s_tvx[w][r] = v; s_tix[w][r] = idx; }
        if ((idx >> 2) == l) {
            int q = idx & 3;
            if (q == 0) a0 = NEG_BIG; else if (q == 1) a1 = NEG_BIG;
            else if (q == 2) a2 = NEG_BIG; else a3 = NEG_BIG;
        }
    }
    for (int r = 0; r < TOPK; r++) {
        float v = b0; int ii = 0;
        if (b1 > v) { v = b1; ii = 1; }
        if (b2 > v) { v = b2; ii = 2; }
        if (b3 > v) { v = b3; ii = 3; }
        int idx = (l << 2) | ii;
        for (int o = 16; o; o >>= 1) {
            float ov = __shfl_xor_sync(~0u, v, o);
            int   oi = __shfl_xor_sync(~0u, idx, o);
            if (ov > v || (ov == v && oi < idx)) { v = ov; idx = oi; }
        }
        if (l == 0) { s_tvy[w][r] = v; s_tiy[w][r] = idx; }
        if ((idx >> 2) == l) {
            int q = idx & 3;
            if (q == 0) b0 = NEG_BIG; else if (q == 1) b1 = NEG_BIG;
            else if (q == 2) b2 = NEG_BIG; else b3 = NEG_BIG;
        }
    }
    __syncwarp();

    float cd[8];
#pragma unroll
    for (int j = 0; j < 8; j++) {
        int c = l * 8 + j;
        cd[j] = s_tvx[w][c >> 4] + s_tvy[w][c & 15];
    }
    for (int r = 0; r < TOPK; r++) {
        float v = cd[0]; int ii = 0;
#pragma unroll
        for (int j = 1; j < 8; j++) if (cd[j] > v) { v = cd[j]; ii = j; }
        int idx = (l << 3) | ii;
        for (int o = 16; o; o >>= 1) {
            float ov = __shfl_xor_sync(~0u, v, o);
            int   oi = __shfl_xor_sync(~0u, idx, o);
            if (ov > v || (ov == v && oi < idx)) { v = ov; idx = oi; }
        }
        if ((idx >> 3) == l) {
            int q = idx & 7;
#pragma unroll
            for (int j = 0; j < 8; j++) if (j == q) cd[j] = NEG_BIG;
        }
        if (l == 0) {
            int a = idx >> 4, b = idx & 15;
            ti[t * TOPK + r] = s_tix[w][a] * S_DIM + s_tiy[w][b];
            tw[t * TOPK + r] = expf(v);
        }
    }
}

// ---------------- Expert v4: 128 threads, fp16 tables + fp16 x ----------------
__global__ void __launch_bounds__(128)
expert_v4(const __half* __restrict__ xh, const __half* __restrict__ ue,
          const __half* __restrict__ de,
          const int* __restrict__ ti, const float* __restrict__ tw,
          float* __restrict__ out)
{
    const int t = blockIdx.x, tid = threadIdx.x;
    const int w = tid >> 5, l = tid & 31;

    __shared__ __half2 xs[H_DIM / 2];
    __shared__ float   acc_s[4][H_DIM];

#pragma unroll
    for (int i = 0; i < 4; i++)
        xs[tid + i * 128] = ((const __half2*)(xh + (size_t)t * H_DIM))[tid + i * 128];
    __syncthreads();

    float4 acc[8];
#pragma unroll
    for (int i = 0; i < 8; i++) acc[i] = make_float4(0.f, 0.f, 0.f, 0.f);

#pragma unroll
    for (int half = 0; half < 4; half++) {
        const int kk = w + half * 4;
        const int e = ti[t * TOPK + kk];
        const __half* ur = ue + (size_t)e * H_DIM;
        float p = 0.f;
#pragma unroll
        for (int i = 0; i < 8; i++) {
            const int f4 = i * 32 + l;
            uint2 raw = *(const uint2*)(ur + f4 * 4);
            __half2 u01 = *reinterpret_cast<const __half2*>(&raw.x);
            __half2 u23 = *reinterpret_cast<const __half2*>(&raw.y);
            float2 a = __half22float2(u01), b = __half22float2(u23);
            float2 x0 = __half22float2(xs[2 * f4]);
            float2 x1 = __half22float2(xs[2 * f4 + 1]);
            p += a.x * x0.x + a.y * x0.y + b.x * x1.x + b.y * x1.y;
        }
#pragma unroll
        for (int o = 16; o; o >>= 1) p += __shfl_xor_sync(~0u, p, o);
        const float coef = tw[t * TOPK + kk] * p;
        const __half* dr = de + (size_t)e * H_DIM;
#pragma unroll
        for (int i = 0; i < 8; i++) {
            const int f4 = i * 32 + l;
            uint2 raw = *(const uint2*)(dr + f4 * 4);
            __half2 d01 = *reinterpret_cast<const __half2*>(&raw.x);
            __half2 d23 = *reinterpret_cast<const __half2*>(&raw.y);
            float2 a = __half22float2(d01), b = __half22float2(d23);
            acc[i].x += coef * a.x; acc[i].y += coef * a.y;
            acc[i].z += coef * b.x; acc[i].w += coef * b.y;
        }
    }
    float4* as = (float4*)acc_s[w];
#pragma unroll
    for (int i = 0; i < 8; i++) as[i * 32 + l] = acc[i];
    __syncthreads();

#pragma unroll
    for (int i = 0; i < 2; i++) {
        const int j = tid + i * 128;
        float4 r = ((const float4*)acc_s[0])[j];
#pragma unroll
        for (int w2 = 1; w2 < 4; w2++) {
            float4 v = ((const float4*)acc_s[w2])[j];
            r.x += v.x; r.y += v.y; r.z += v.z; r.w += v.w;
        }
        ((float4*)(out + (size_t)t * H_DIM))[j] = r;
    }
}

// ---------------- launch (two-stream, graph-capturable) ----------------
extern "C" void kernel_launch(void* const* d_in, const int* in_sizes, int n_in,
                              void* d_out, int out_size)
{
    const float* x   = (const float*)d_in[0];
    const float* wg  = (const float*)d_in[1];
    const float* wu  = (const float*)d_in[2];
    const float* wd  = (const float*)d_in[3];
    const float* wrx = (const float*)d_in[4];
    const float* wry = (const float*)d_in[5];
    const float* ue  = (const float*)d_in[6];
    const float* de  = (const float*)d_in[7];
    float* out = (float*)d_out;

    __half *xh, *wgu, *wdh, *wrh, *ueh, *deh, *hh;
    float *gxy, *bnp, *bn, *tw;
    int* ti;
    cudaGetSymbolAddress((void**)&xh, g_xh);
    cudaGetSymbolAddress((void**)&wgu, g_wgu);
    cudaGetSymbolAddress((void**)&wdh, g_wdh);
    cudaGetSymbolAddress((void**)&wrh, g_wrh);
    cudaGetSymbolAddress((void**)&ueh, g_ueh);
    cudaGetSymbolAddress((void**)&deh, g_deh);
    cudaGetSymbolAddress((void**)&hh, g_hh);
    cudaGetSymbolAddress((void**)&gxy, g_gxy);
    cudaGetSymbolAddress((void**)&bnp, g_bnp);
    cudaGetSymbolAddress((void**)&bn, g_bn);
    cudaGetSymbolAddress((void**)&ti, g_ti);
    cudaGetSymbolAddress((void**)&tw, g_tw);

    static cudaStream_t s2 = nullptr;
    static cudaEvent_t ev0 = nullptr, ev1 = nullptr, ev_join = nullptr;
    if (!s2) {
        cudaStreamCreateWithFlags(&s2, cudaStreamNonBlocking);
        cudaEventCreateWithFlags(&ev0, cudaEventDisableTiming);
        cudaEventCreateWithFlags(&ev1, cudaEventDisableTiming);
        cudaEventCreateWithFlags(&ev_join, cudaEventDisableTiming);
    }

    constexpr int SMEM = 3 * 2 * 128 * 64;  // 48 KB, occ 2
    const int SH = S_DIM * H_DIM;

    // fork 0: side stream conversions start immediately (wd off the main path)
    cudaEventRecord(ev0, 0);
    cudaStreamWaitEvent(s2, ev0, 0);
    conv_half<<<2048, 256, 0, s2>>>((const float4*)wd, (__half2*)wdh, H_DIM * I_DIM / 4);
    conv_half<<<2048, 256, 0, s2>>>((const float4*)ue, (__half2*)ueh, E_NUM * H_DIM / 4);
    conv_half<<<2048, 256, 0, s2>>>((const float4*)de, (__half2*)deh, E_NUM * H_DIM / 4);
    conv_half<<<128, 256, 0, s2>>>((const float4*)wrx, (__half2*)wrh, SH / 4);
    conv_half<<<128, 256, 0, s2>>>((const float4*)wry, (__half2*)(wrh + SH), SH / 4);

    // main: conv x, then fork 1 IMMEDIATELY (side chain needs only xh)
    conv_half<<<2048, 256>>>((const float4*)x, (__half2*)xh, T_TOK * H_DIM / 4);
    cudaEventRecord(ev1, 0);

    // side: router chain + expert branch (starts as soon as xh is ready)
    cudaStreamWaitEvent(s2, ev1, 0);
    gemm_mma<0><<<dim3(2, T_TOK / 128), 256, SMEM, s2>>>(
        xh, wrh, H_DIM, H_DIM / 32, 2 * S_DIM, gxy, nullptr);
    bn_partial<<<128, 256, 0, s2>>>((const float4*)gxy, bnp);
    bn_final<<<1, 256, 0, s2>>>(bnp, bn);
    router_warp<<<T_TOK / 4, 128, 0, s2>>>(gxy, bn, ti, tw);
    expert_v4<<<T_TOK, 128, 0, s2>>>(xh, ueh, deh, ti, tw, out);
    cudaEventRecord(ev_join, s2);

    // main: interleave then fused gate+up (fp32-acc, EPI=3)
    conv_interleave<<<2048, 256>>>((const float4*)wg, (const float4*)wu,
                                   (__half2*)wgu, I_DIM * H_DIM / 4);
    gemm_mma<3><<<dim3(2 * I_DIM / 128, T_TOK / 128), 256, SMEM>>>(
        xh, wgu, H_DIM, H_DIM / 32, 2 * I_DIM, nullptr, hh);

    // join: down GEMM (fp32-acc) accumulates onto expert output
    cudaStreamWaitEvent(0, ev_join, 0);
    gemm_mma<2><<<dim3(H_DIM / 128, T_TOK / 128), 256, SMEM>>>(
        hh, wdh, I_DIM, I_DIM / 32, H_DIM, out, nullptr);
}

// round 16
// speedup vs baseline: 1.1890x; 1.0136x over previous
#include <cuda_runtime.h>
#include <cuda_fp16.h>
#include <math.h>
#include <stdint.h>

#define T_TOK 8192
#define H_DIM 1024
#define I_DIM 4096
#define S_DIM 128
#define E_NUM 16384
#define TOPK  16

// ---------------- scratch ----------------
__device__ __align__(16) __half g_xh  [(size_t)T_TOK * H_DIM];
__device__ __align__(16) __half g_wgu [(size_t)2 * I_DIM * H_DIM];   // interleaved [wg_j; wu_j]
__device__ __align__(16) __half g_wdh [(size_t)H_DIM * I_DIM];
__device__ __align__(16) __half g_wrh [(size_t)2 * S_DIM * H_DIM];   // [wrx; wry]
__device__ __align__(16) __half g_ueh [(size_t)E_NUM * H_DIM];
__device__ __align__(16) __half g_deh [(size_t)E_NUM * H_DIM];
__device__ __align__(16) __half g_hh  [(size_t)T_TOK * I_DIM];
__device__ __align__(16) float  g_gxy [(size_t)T_TOK * 2 * S_DIM];   // [T, 256]
__device__ __align__(16) float  g_bnp [128 * 512];
__device__ __align__(16) float  g_bn  [4 * S_DIM];
__device__ __align__(16) int    g_ti  [(size_t)T_TOK * TOPK];
__device__ __align__(16) float  g_tw  [(size_t)T_TOK * TOPK];

// ---------------- PTX helpers (sm_80-compatible only) ----------------
__device__ __forceinline__ uint32_t s2u(const void* p) {
    uint32_t a;
    asm("{ .reg .u64 t; cvta.to.shared.u64 t, %1; cvt.u32.u64 %0, t; }" : "=r"(a) : "l"(p));
    return a;
}
__device__ __forceinline__ void cp16(uint32_t dst, const void* src) {
    asm volatile("cp.async.cg.shared.global [%0], [%1], 16;" :: "r"(dst), "l"(src));
}
#define CP_COMMIT() asm volatile("cp.async.commit_group;" ::: "memory")
#define CP_WAIT(N)  asm volatile("cp.async.wait_group %0;" :: "n"(N) : "memory")

__device__ __forceinline__ void ldm4(uint32_t* r, uint32_t addr) {
    asm volatile("ldmatrix.sync.aligned.m8n8.x4.shared.b16 {%0,%1,%2,%3}, [%4];"
                 : "=r"(r[0]), "=r"(r[1]), "=r"(r[2]), "=r"(r[3]) : "r"(addr));
}
__device__ __forceinline__ void mma16816(float* c, const uint32_t* a, uint32_t b0, uint32_t b1) {
    asm volatile("mma.sync.aligned.m16n8k16.row.col.f32.f16.f16.f32 "
                 "{%0,%1,%2,%3}, {%4,%5,%6,%7}, {%8,%9}, {%0,%1,%2,%3};"
                 : "+f"(c[0]), "+f"(c[1]), "+f"(c[2]), "+f"(c[3])
                 : "r"(a[0]), "r"(a[1]), "r"(a[2]), "r"(a[3]), "r"(b0), "r"(b1));
}

// smem tile: 128 rows x 32 f16 (64B/row); chunk = 16B of 8 f16.
// swizzle: chunk' = chunk ^ ((row>>1)&3)
__device__ __forceinline__ uint32_t tile_off(int row, int chunk) {
    return (uint32_t)row * 64u + (uint32_t)((chunk ^ ((row >> 1) & 3)) * 16);
}

// ---------------- fp32 -> fp16 (2x ILP) ----------------
__global__ void conv_half(const float4* __restrict__ in, __half2* __restrict__ o, int n4)
{
    const int stride = gridDim.x * blockDim.x;
    int i = blockIdx.x * blockDim.x + threadIdx.x;
    for (; i + stride < n4; i += 2 * stride) {
        float4 v0 = in[i];
        float4 v1 = in[i + stride];
        o[2 * i]     = __half2{__float2half_rn(v0.x), __float2half_rn(v0.y)};
        o[2 * i + 1] = __half2{__float2half_rn(v0.z), __float2half_rn(v0.w)};
        o[2 * (i + stride)]     = __half2{__float2half_rn(v1.x), __float2half_rn(v1.y)};
        o[2 * (i + stride) + 1] = __half2{__float2half_rn(v1.z), __float2half_rn(v1.w)};
    }
    if (i < n4) {
        float4 v = in[i];
        o[2 * i]     = __half2{__float2half_rn(v.x), __float2half_rn(v.y)};
        o[2 * i + 1] = __half2{__float2half_rn(v.z), __float2half_rn(v.w)};
    }
}

// interleave wg/wu rows: W'[2j] = wg[j], W'[2j+1] = wu[j]  (fp32 -> fp16)
__global__ void conv_interleave(const float4* __restrict__ wg, const float4* __restrict__ wu,
                                __half2* __restrict__ o, int n4)   // n4 = I*H/4
{
    constexpr int H4 = H_DIM / 4;
    for (int i = blockIdx.x * blockDim.x + threadIdx.x; i < n4; i += gridDim.x * blockDim.x) {
        int row = i / H4, c = i % H4;
        float4 g = wg[i], u = wu[i];
        size_t dg = (size_t)(2 * row) * H4 + c;
        size_t du = (size_t)(2 * row + 1) * H4 + c;
        o[2 * dg]     = __half2{__float2half_rn(g.x), __float2half_rn(g.y)};
        o[2 * dg + 1] = __half2{__float2half_rn(g.z), __float2half_rn(g.w)};
        o[2 * du]     = __half2{__float2half_rn(u.x), __float2half_rn(u.y)};
        o[2 * du + 1] = __half2{__float2half_rn(u.z), __float2half_rn(u.w)};
    }
}

// ---------------------------------------------------------------------------
// fp16 single-pass GEMM, fp32 accumulate — measured-best config (R12).
// EPI: 0 = C = D;  2 = C += D;
//      3 = interleaved gate/up: col pair (2j,2j+1) -> h_j = silu(D_2j)*D_2j+1 -> Hh fp16
// ---------------------------------------------------------------------------
template<int EPI>
__global__ void __launch_bounds__(256, 2)
gemm_mma(const __half* __restrict__ A, const __half* __restrict__ B,
         int K, int niter, int N,
         float* __restrict__ C, __half* __restrict__ Hh)
{
    constexpr uint32_t TILE = 128 * 64;
    constexpr uint32_t STAGE = 2 * TILE;
    extern __shared__ char smem[];
    const uint32_t sbase = s2u(smem);

    const int tid  = threadIdx.x;
    const int lane = tid & 31;
    const int wid  = tid >> 5;
    const int wm   = wid >> 1;
    const int wn   = wid & 1;
    const int bm   = blockIdx.y * 128;
    const int bn   = blockIdx.x * 128;

    const int prow = tid >> 1;
    const int pc0  = (tid & 1) * 2;
    const uint32_t pa_off0 = tile_off(prow, pc0);
    const uint32_t pa_off1 = tile_off(prow, pc0 + 1);

    const int lrow8 = ((lane >> 3) & 1) * 8 + (lane & 7);
    const int lchnk = lane >> 4;
    uint32_t a_off[2], b_off[4];
#pragma unroll
    for (int mt = 0; mt < 2; mt++)
        a_off[mt] = tile_off(wm * 32 + mt * 16 + lrow8, lchnk);
#pragma unroll
    for (int p = 0; p < 4; p++)
        b_off[p] = tile_off(wn * 64 + p * 16 + lrow8, lchnk);

    float acc[2][8][4];
#pragma unroll
    for (int mt = 0; mt < 2; mt++)
#pragma unroll
        for (int nt = 0; nt < 8; nt++)
#pragma unroll
            for (int q = 0; q < 4; q++) acc[mt][nt][q] = 0.f;

    auto load_stage = [&](int j) {
        const int kk = j * 32;
        const uint32_t sa = sbase + (uint32_t)(j % 3) * STAGE;
        const uint32_t sb = sa + TILE;
        const __half* ga = A + (size_t)(bm + prow) * K + kk + pc0 * 8;
        const __half* gb = B + (size_t)(bn + prow) * K + kk + pc0 * 8;
        cp16(sa + pa_off0, ga);
        cp16(sa + pa_off1, ga + 8);
        cp16(sb + pa_off0, gb);
        cp16(sb + pa_off1, gb + 8);
    };

    load_stage(0); CP_COMMIT();
    load_stage(1); CP_COMMIT();

    for (int j = 0; j < niter; ++j) {
        CP_WAIT(1);
        __syncthreads();
        if (j + 2 < niter) load_stage(j + 2);
        CP_COMMIT();

        const uint32_t sa = sbase + (uint32_t)(j % 3) * STAGE;
        const uint32_t sb = sa + TILE;
#pragma unroll
        for (int ks = 0; ks < 2; ks++) {
            const uint32_t kx = ks ? 32u : 0u;
            uint32_t a[2][4], b[4][4];
#pragma unroll
            for (int mt = 0; mt < 2; mt++) ldm4(a[mt], sa + (a_off[mt] ^ kx));
#pragma unroll
            for (int p = 0; p < 4; p++)    ldm4(b[p], sb + (b_off[p] ^ kx));
#pragma unroll
            for (int mt = 0; mt < 2; mt++)
#pragma unroll
                for (int p = 0; p < 4; p++) {
                    mma16816(acc[mt][2 * p],     a[mt], b[p][0], b[p][2]);
                    mma16816(acc[mt][2 * p + 1], a[mt], b[p][1], b[p][3]);
                }
        }
    }

    const int gid  = lane >> 2;
    const int tid4 = lane & 3;
#pragma unroll
    for (int mt = 0; mt < 2; mt++) {
        const int r0 = bm + wm * 32 + mt * 16 + gid;
        const int r1 = r0 + 8;
#pragma unroll
        for (int nt = 0; nt < 8; nt++) {
            const int col = bn + wn * 64 + nt * 8 + tid4 * 2;
            float v00 = acc[mt][nt][0], v01 = acc[mt][nt][1];
            float v10 = acc[mt][nt][2], v11 = acc[mt][nt][3];
            if (EPI == 0) {
                *(float2*)(C + (size_t)r0 * N + col) = make_float2(v00, v01);
                *(float2*)(C + (size_t)r1 * N + col) = make_float2(v10, v11);
            } else if (EPI == 2) {
                float2 c0 = *(float2*)(C + (size_t)r0 * N + col);
                float2 c1 = *(float2*)(C + (size_t)r1 * N + col);
                *(float2*)(C + (size_t)r0 * N + col) = make_float2(c0.x + v00, c0.y + v01);
                *(float2*)(C + (size_t)r1 * N + col) = make_float2(c1.x + v10, c1.y + v11);
            } else {
                const int hw = N >> 1;
                const int jj = col >> 1;
                float h0 = v00 / (1.f + expf(-v00)) * v01;
                float h1 = v10 / (1.f + expf(-v10)) * v11;
                Hh[(size_t)r0 * hw + jj] = __float2half_rn(h0);
                Hh[(size_t)r1 * hw + jj] = __float2half_rn(h1);
            }
        }
    }
}

// ---------------- BatchNorm stats, coalesced two-phase ----------------
__global__ void __launch_bounds__(256)
bn_partial(const float4* __restrict__ gxy4, float* __restrict__ part)
{
    const int b = blockIdx.x, tid = threadIdx.x;
    const int col = tid & 63;
    const int rp  = tid >> 6;
    float4 s = make_float4(0.f, 0.f, 0.f, 0.f);
    float4 q = make_float4(0.f, 0.f, 0.f, 0.f);
    const int base = b * 64;
#pragma unroll
    for (int p = 0; p < 16; p++) {
        float4 v = gxy4[(size_t)(base + p * 4 + rp) * 64 + col];
        s.x += v.x; s.y += v.y; s.z += v.z; s.w += v.w;
        q.x += v.x * v.x; q.y += v.y * v.y; q.z += v.z * v.z; q.w += v.w * v.w;
    }
    __shared__ float4 ss[256], qq[256];
    ss[tid] = s; qq[tid] = q;
    __syncthreads();
    if (tid < 64) {
        float4 S = ss[tid], Q = qq[tid];
#pragma unroll
        for (int k = 1; k < 4; k++) {
            float4 a = ss[tid + 64 * k], c = qq[tid + 64 * k];
            S.x += a.x; S.y += a.y; S.z += a.z; S.w += a.w;
            Q.x += c.x; Q.y += c.y; Q.z += c.z; Q.w += c.w;
        }
        ((float4*)(part + (size_t)b * 512))[tid]       = S;
        ((float4*)(part + (size_t)b * 512 + 256))[tid] = Q;
    }
}

__global__ void __launch_bounds__(256)
bn_final(const float* __restrict__ part, float* __restrict__ bn)
{
    const int fb = threadIdx.x;
    float s = 0.f, q = 0.f;
    for (int b = 0; b < 128; b++) {
        s += part[(size_t)b * 512 + fb];
        q += part[(size_t)b * 512 + 256 + fb];
    }
    float mean = s / (float)T_TOK;
    float var  = q / (float)T_TOK - mean * mean;
    const int f = fb & (S_DIM - 1);
    const int base = (fb < S_DIM) ? 0 : 2;
    bn[base * S_DIM + f]       = mean;
    bn[(base + 1) * S_DIM + f] = rsqrtf(var + 1e-5f);
}

// ---------------- Router: one warp per token ----------------
#define NEG_BIG (-1e30f)
__global__ void __launch_bounds__(128)
router_warp(const float* __restrict__ gxy, const float* __restrict__ bn,
            int* __restrict__ ti, float* __restrict__ tw)
{
    const int w = threadIdx.x >> 5, l = threadIdx.x & 31;
    const int t = blockIdx.x * 4 + w;

    __shared__ float s_tvx[4][16], s_tvy[4][16];
    __shared__ int   s_tix[4][16], s_tiy[4][16];

    const float4 mux = ((const float4*)bn)[l];
    const float4 ivx = ((const float4*)bn)[32 + l];
    const float4 muy = ((const float4*)bn)[64 + l];
    const float4 ivy = ((const float4*)bn)[96 + l];

    float4 vx = ((const float4*)(gxy + (size_t)t * 256))[l];
    float4 vy = ((const float4*)(gxy + (size_t)t * 256))[32 + l];
    vx.x = (vx.x - mux.x) * ivx.x; vx.y = (vx.y - mux.y) * ivx.y;
    vx.z = (vx.z - mux.z) * ivx.z; vx.w = (vx.w - mux.w) * ivx.w;
    vy.x = (vy.x - muy.x) * ivy.x; vy.y = (vy.y - muy.y) * ivy.y;
    vy.z = (vy.z - muy.z) * ivy.z; vy.w = (vy.w - muy.w) * ivy.w;

    float m = fmaxf(fmaxf(vx.x, vx.y), fmaxf(vx.z, vx.w));
    for (int o = 16; o; o >>= 1) m = fmaxf(m, __shfl_xor_sync(~0u, m, o));
    float se = expf(vx.x - m) + expf(vx.y - m) + expf(vx.z - m) + expf(vx.w - m);
    for (int o = 16; o; o >>= 1) se += __shfl_xor_sync(~0u, se, o);
    float ls = m + logf(se);
    float a0 = vx.x - ls, a1 = vx.y - ls, a2 = vx.z - ls, a3 = vx.w - ls;

    m = fmaxf(fmaxf(vy.x, vy.y), fmaxf(vy.z, vy.w));
    for (int o = 16; o; o >>= 1) m = fmaxf(m, __shfl_xor_sync(~0u, m, o));
    se = expf(vy.x - m) + expf(vy.y - m) + expf(vy.z - m) + expf(vy.w - m);
    for (int o = 16; o; o >>= 1) se += __shfl_xor_sync(~0u, se, o);
    ls = m + logf(se);
    float b0 = vy.x - ls, b1 = vy.y - ls, b2 = vy.z - ls, b3 = vy.w - ls;

    for (int r = 0; r < TOPK; r++) {
        float v = a0; int ii = 0;
        if (a1 > v) { v = a1; ii = 1; }
        if (a2 > v) { v = a2; ii = 2; }
        if (a3 > v) { v = a3; ii = 3; }
        int idx = (l << 2) | ii;
        for (int o = 16; o; o >>= 1) {
            float ov = __shfl_xor_sync(~0u, v, o);
            int   oi = __shfl_xor_sync(~0u, idx, o);
            if (ov > v || (ov == v && oi < idx)) { v = ov; idx = oi; }
        }
        if (l == 0) { s_tvx[w][r] = v; s_tix[w][r] = idx; }
        if ((idx >> 2) == l) {
            int q = idx & 3;
            if (q == 0) a0 = NEG_BIG; else if (q == 1) a1 = NEG_BIG;
            else if (q == 2) a2 = NEG_BIG; else a3 = NEG_BIG;
        }
    }
    for (int r = 0; r < TOPK; r++) {
        float v = b0; int ii = 0;
        if (b1 > v) { v = b1; ii = 1; }
        if (b2 > v) { v = b2; ii = 2; }
        if (b3 > v) { v = b3; ii = 3; }
        int idx = (l << 2) | ii;
        for (int o = 16; o; o >>= 1) {
            float ov = __shfl_xor_sync(~0u, v, o);
            int   oi = __shfl_xor_sync(~0u, idx, o);
            if (ov > v || (ov == v && oi < idx)) { v = ov; idx = oi; }
        }
        if (l == 0) { s_tvy[w][r] = v; s_tiy[w][r] = idx; }
        if ((idx >> 2) == l) {
            int q = idx & 3;
            if (q == 0) b0 = NEG_BIG; else if (q == 1) b1 = NEG_BIG;
            else if (q == 2) b2 = NEG_BIG; else b3 = NEG_BIG;
        }
    }
    __syncwarp();

    float cd[8];
#pragma unroll
    for (int j = 0; j < 8; j++) {
        int c = l * 8 + j;
        cd[j] = s_tvx[w][c >> 4] + s_tvy[w][c & 15];
    }
    for (int r = 0; r < TOPK; r++) {
        float v = cd[0]; int ii = 0;
#pragma unroll
        for (int j = 1; j < 8; j++) if (cd[j] > v) { v = cd[j]; ii = j; }
        int idx = (l << 3) | ii;
        for (int o = 16; o; o >>= 1) {
            float ov = __shfl_xor_sync(~0u, v, o);
            int   oi = __shfl_xor_sync(~0u, idx, o);
            if (ov > v || (ov == v && oi < idx)) { v = ov; idx = oi; }
        }
        if ((idx >> 3) == l) {
            int q = idx & 7;
#pragma unroll
            for (int j = 0; j < 8; j++) if (j == q) cd[j] = NEG_BIG;
        }
        if (l == 0) {
            int a = idx >> 4, b = idx & 15;
            ti[t * TOPK + r] = s_tix[w][a] * S_DIM + s_tiy[w][b];
            tw[t * TOPK + r] = expf(v);
        }
    }
}

// ---------------- Expert v4: 128 threads, fp16 tables + fp16 x ----------------
__global__ void __launch_bounds__(128)
expert_v4(const __half* __restrict__ xh, const __half* __restrict__ ue,
          const __half* __restrict__ de,
          const int* __restrict__ ti, const float* __restrict__ tw,
          float* __restrict__ out)
{
    const int t = blockIdx.x, tid = threadIdx.x;
    const int w = tid >> 5, l = tid & 31;

    __shared__ __half2 xs[H_DIM / 2];
    __shared__ float   acc_s[4][H_DIM];

#pragma unroll
    for (int i = 0; i < 4; i++)
        xs[tid + i * 128] = ((const __half2*)(xh + (size_t)t * H_DIM))[tid + i * 128];
    __syncthreads();

    float4 acc[8];
#pragma unroll
    for (int i = 0; i < 8; i++) acc[i] = make_float4(0.f, 0.f, 0.f, 0.f);

#pragma unroll
    for (int half = 0; half < 4; half++) {
        const int kk = w + half * 4;
        const int e = ti[t * TOPK + kk];
        const __half* ur = ue + (size_t)e * H_DIM;
        float p = 0.f;
#pragma unroll
        for (int i = 0; i < 8; i++) {
            const int f4 = i * 32 + l;
            uint2 raw = *(const uint2*)(ur + f4 * 4);
            __half2 u01 = *reinterpret_cast<const __half2*>(&raw.x);
            __half2 u23 = *reinterpret_cast<const __half2*>(&raw.y);
            float2 a = __half22float2(u01), b = __half22float2(u23);
            float2 x0 = __half22float2(xs[2 * f4]);
            float2 x1 = __half22float2(xs[2 * f4 + 1]);
            p += a.x * x0.x + a.y * x0.y + b.x * x1.x + b.y * x1.y;
        }
#pragma unroll
        for (int o = 16; o; o >>= 1) p += __shfl_xor_sync(~0u, p, o);
        const float coef = tw[t * TOPK + kk] * p;
        const __half* dr = de + (size_t)e * H_DIM;
#pragma unroll
        for (int i = 0; i < 8; i++) {
            const int f4 = i * 32 + l;
            uint2 raw = *(const uint2*)(dr + f4 * 4);
            __half2 d01 = *reinterpret_cast<const __half2*>(&raw.x);
            __half2 d23 = *reinterpret_cast<const __half2*>(&raw.y);
            float2 a = __half22float2(d01), b = __half22float2(d23);
            acc[i].x += coef * a.x; acc[i].y += coef * a.y;
            acc[i].z += coef * b.x; acc[i].w += coef * b.y;
        }
    }
    float4* as = (float4*)acc_s[w];
#pragma unroll
    for (int i = 0; i < 8; i++) as[i * 32 + l] = acc[i];
    __syncthreads();

#pragma unroll
    for (int i = 0; i < 2; i++) {
        const int j = tid + i * 128;
        float4 r = ((const float4*)acc_s[0])[j];
#pragma unroll
        for (int w2 = 1; w2 < 4; w2++) {
            float4 v = ((const float4*)acc_s[w2])[j];
            r.x += v.x; r.y += v.y; r.z += v.z; r.w += v.w;
        }
        ((float4*)(out + (size_t)t * H_DIM))[j] = r;
    }
}

// ---------------- launch (two-stream, graph-capturable, DRAM-balanced) ----------------
extern "C" void kernel_launch(void* const* d_in, const int* in_sizes, int n_in,
                              void* d_out, int out_size)
{
    const float* x   = (const float*)d_in[0];
    const float* wg  = (const float*)d_in[1];
    const float* wu  = (const float*)d_in[2];
    const float* wd  = (const float*)d_in[3];
    const float* wrx = (const float*)d_in[4];
    const float* wry = (const float*)d_in[5];
    const float* ue  = (const float*)d_in[6];
    const float* de  = (const float*)d_in[7];
    float* out = (float*)d_out;

    __half *xh, *wgu, *wdh, *wrh, *ueh, *deh, *hh;
    float *gxy, *bnp, *bn, *tw;
    int* ti;
    cudaGetSymbolAddress((void**)&xh, g_xh);
    cudaGetSymbolAddress((void**)&wgu, g_wgu);
    cudaGetSymbolAddress((void**)&wdh, g_wdh);
    cudaGetSymbolAddress((void**)&wrh, g_wrh);
    cudaGetSymbolAddress((void**)&ueh, g_ueh);
    cudaGetSymbolAddress((void**)&deh, g_deh);
    cudaGetSymbolAddress((void**)&hh, g_hh);
    cudaGetSymbolAddress((void**)&gxy, g_gxy);
    cudaGetSymbolAddress((void**)&bnp, g_bnp);
    cudaGetSymbolAddress((void**)&bn, g_bn);
    cudaGetSymbolAddress((void**)&ti, g_ti);
    cudaGetSymbolAddress((void**)&tw, g_tw);

    static cudaStream_t s2 = nullptr;
    static cudaEvent_t ev0 = nullptr, ev1 = nullptr, ev_join = nullptr;
    if (!s2) {
        cudaStreamCreateWithFlags(&s2, cudaStreamNonBlocking);
        cudaEventCreateWithFlags(&ev0, cudaEventDisableTiming);
        cudaEventCreateWithFlags(&ev1, cudaEventDisableTiming);
        cudaEventCreateWithFlags(&ev_join, cudaEventDisableTiming);
    }

    constexpr int SMEM = 3 * 2 * 128 * 64;  // 48 KB, occ 2
    const int SH = S_DIM * H_DIM;

    // fork 0: side stream — ONLY the tiny router-weight convs early
    // (big table/wd convs deferred to DRAM-quiet phases)
    cudaEventRecord(ev0, 0);
    cudaStreamWaitEvent(s2, ev0, 0);
    conv_half<<<128, 256, 0, s2>>>((const float4*)wrx, (__half2*)wrh, SH / 4);
    conv_half<<<128, 256, 0, s2>>>((const float4*)wry, (__half2*)(wrh + SH), SH / 4);

    // main: conv x, fork 1 immediately (side chain needs only xh)
    conv_half<<<2048, 256>>>((const float4*)x, (__half2*)xh, T_TOK * H_DIM / 4);
    cudaEventRecord(ev1, 0);

    // side: router chain; ue/de conversions deferred until the gateup-GEMM
    // window (DRAM <10% there), right before the expert needs them
    cudaStreamWaitEvent(s2, ev1, 0);
    gemm_mma<0><<<dim3(2, T_TOK / 128), 256, SMEM, s2>>>(
        xh, wrh, H_DIM, H_DIM / 32, 2 * S_DIM, gxy, nullptr);
    bn_partial<<<128, 256, 0, s2>>>((const float4*)gxy, bnp);
    bn_final<<<1, 256, 0, s2>>>(bnp, bn);
    router_warp<<<T_TOK / 4, 128, 0, s2>>>(gxy, bn, ti, tw);
    conv_half<<<2048, 256, 0, s2>>>((const float4*)ue, (__half2*)ueh, E_NUM * H_DIM / 4);
    conv_half<<<2048, 256, 0, s2>>>((const float4*)de, (__half2*)deh, E_NUM * H_DIM / 4);
    expert_v4<<<T_TOK, 128, 0, s2>>>(xh, ueh, deh, ti, tw, out);
    cudaEventRecord(ev_join, s2);

    // main: interleave, fused gate+up, then wd conv in the post-GEMM DRAM-idle slot
    conv_interleave<<<2048, 256>>>((const float4*)wg, (const float4*)wu,
                                   (__half2*)wgu, I_DIM * H_DIM / 4);
    gemm_mma<3><<<dim3(2 * I_DIM / 128, T_TOK / 128), 256, SMEM>>>(
        xh, wgu, H_DIM, H_DIM / 32, 2 * I_DIM, nullptr, hh);
    conv_half<<<2048, 256>>>((const float4*)wd, (__half2*)wdh, H_DIM * I_DIM / 4);

    // join: down GEMM accumulates onto expert output
    cudaStreamWaitEvent(0, ev_join, 0);
    gemm_mma<2><<<dim3(H_DIM / 128, T_TOK / 128), 256, SMEM>>>(
        hh, wdh, I_DIM, I_DIM / 32, H_DIM, out, nullptr);
}